// round 2
// baseline (speedup 1.0000x reference)
#include <cuda_runtime.h>
#include <math.h>

#define BB 2
#define LL 8192
#define DIMV 512
#define NH 8
#define HD 64
#define SCALE 0.125f
#define NEG_FILL -100000000.0f
#define ML (BB*LL)   // 16384 rows total

// ---------------- scratch (static device arrays; no allocation) ----------------
__device__ float g_q[ML*DIMV];
__device__ float g_k[ML*DIMV];
__device__ float g_v[ML*DIMV];
__device__ float g_o0[ML*DIMV];   // branch outputs (only covered slots ever written;
__device__ float g_o1[ML*DIMV];   //  uncovered stay 0 from static init and are
__device__ float g_o2[ML*DIMV];   //  masked by the analytic coverage predicate)
__device__ float g_l0[ML*NH];
__device__ float g_l1[ML*NH];
__device__ float g_l2[ML*NH];
__device__ float g_comb[ML*DIMV];

// =====================================================================
// GEMM: C[16384,512] = A[16384,512] @ W[512,512]^T (+bias)
// CTA tile 128x128, 256 threads, 8x8 microtile, BK=16
// =====================================================================
__global__ __launch_bounds__(256) void gemm_xt(const float* __restrict__ A,
                                               const float* __restrict__ W,
                                               const float* __restrict__ bias,
                                               float* __restrict__ C) {
    __shared__ __align__(16) float As[16][132];
    __shared__ __align__(16) float Bs[16][132];
    const int t  = threadIdx.x;
    const int tx = t & 15, ty = t >> 4;
    const int m0 = blockIdx.x * 128, n0 = blockIdx.y * 128;

    float acc[8][8];
    #pragma unroll
    for (int i = 0; i < 8; i++)
        #pragma unroll
        for (int j = 0; j < 8; j++) acc[i][j] = 0.f;

    for (int k0 = 0; k0 < 512; k0 += 16) {
        #pragma unroll
        for (int rr = 0; rr < 2; rr++) {
            int f   = t + rr * 256;
            int row = f >> 2;
            int kc  = (f & 3) << 2;
            float4 a = *(const float4*)(A + (size_t)(m0 + row) * 512 + k0 + kc);
            As[kc+0][row] = a.x; As[kc+1][row] = a.y;
            As[kc+2][row] = a.z; As[kc+3][row] = a.w;
            float4 b = *(const float4*)(W + (size_t)(n0 + row) * 512 + k0 + kc);
            Bs[kc+0][row] = b.x; Bs[kc+1][row] = b.y;
            Bs[kc+2][row] = b.z; Bs[kc+3][row] = b.w;
        }
        __syncthreads();
        #pragma unroll
        for (int kk = 0; kk < 16; kk++) {
            float4 a0 = *(const float4*)&As[kk][ty*8];
            float4 a1 = *(const float4*)&As[kk][ty*8+4];
            float4 b0 = *(const float4*)&Bs[kk][tx*8];
            float4 b1 = *(const float4*)&Bs[kk][tx*8+4];
            float av[8] = {a0.x,a0.y,a0.z,a0.w,a1.x,a1.y,a1.z,a1.w};
            float bv[8] = {b0.x,b0.y,b0.z,b0.w,b1.x,b1.y,b1.z,b1.w};
            #pragma unroll
            for (int i = 0; i < 8; i++)
                #pragma unroll
                for (int j = 0; j < 8; j++)
                    acc[i][j] += av[i] * bv[j];
        }
        __syncthreads();
    }

    #pragma unroll
    for (int i = 0; i < 8; i++) {
        int m = m0 + ty*8 + i;
        float4 r0 = make_float4(acc[i][0], acc[i][1], acc[i][2], acc[i][3]);
        float4 r1 = make_float4(acc[i][4], acc[i][5], acc[i][6], acc[i][7]);
        if (bias) {
            float4 c0 = *(const float4*)(bias + n0 + tx*8);
            float4 c1 = *(const float4*)(bias + n0 + tx*8 + 4);
            r0.x += c0.x; r0.y += c0.y; r0.z += c0.z; r0.w += c0.w;
            r1.x += c1.x; r1.y += c1.y; r1.z += c1.z; r1.w += c1.w;
        }
        *(float4*)(C + (size_t)m * 512 + n0 + tx*8)     = r0;
        *(float4*)(C + (size_t)m * 512 + n0 + tx*8 + 4) = r1;
    }
}

// =====================================================================
// Flash attention over the dilated gather.
// Each CTA: one (branch, batch, segment, head, q-tile of 128 rows).
// 224 attention blocks x 8 q-tiles = 1792 CTAs, 256 threads (16x16),
// microtile: 8 q-rows x 4 k-cols (scores) / 8 q-rows x 4 d-cols (output).
// K tiles of 64, online softmax, P routed through shared memory.
// =====================================================================
#define QSTR 132   // Qs stride (d-major), 528B = 33*16
#define KSTR 68    // Ks/Vs/Ps stride, 272B = 17*16
#define ATTN_SMEM_FLOATS (64*QSTR + 64*KSTR + 64*KSTR + 128*KSTR)  // 25856
#define ATTN_SMEM_BYTES  (ATTN_SMEM_FLOATS * 4)                    // 103424

__global__ __launch_bounds__(256, 2) void attn_kernel() {
    extern __shared__ __align__(16) float sm[];
    float* Qs = sm;                    // [64][QSTR]  Q^T (d-major), pre-scaled
    float* Ks = Qs + 64*QSTR;          // [64][KSTR]  K^T (d-major)
    float* Vs = Ks + 64*KSTR;          // [64][KSTR]  V   (n-major)
    float* Ps = Vs + 64*KSTR;          // [128][KSTR] P   (m-major)

    int bid = blockIdx.x;
    int br, rem;
    if (bid < 1024)      { br = 0; rem = bid; }
    else if (bid < 1536) { br = 1; rem = bid - 1024; }
    else                 { br = 2; rem = bid - 1536; }

    int sl, dr, nseg;
    if (br == 0)      { sl = 1024; dr = 1; nseg = 8; }
    else if (br == 1) { sl = 2048; dr = 2; nseg = 4; }
    else              { sl = 4096; dr = 4; nseg = 2; }

    int qt = rem & 7; rem >>= 3;
    int h  = rem & 7; rem >>= 3;
    int seg = rem % nseg;
    int b   = rem / nseg;
    int off = h / (NH / dr);           // h // hsub

    float* og = (br == 0) ? g_o0 : (br == 1) ? g_o1 : g_o2;
    float* lg = (br == 0) ? g_l0 : (br == 1) ? g_l1 : g_l2;

    const int t  = threadIdx.x;
    const int tx = t & 15, ty = t >> 4;
    const size_t baseBL = (size_t)b * LL;

    // ---- load Q tile (128 rows x 64 d), transposed + pre-scaled ----
    {
        int f4 = (t & 15) << 2;
        int rl = t >> 4;
        #pragma unroll
        for (int r = 0; r < 8; r++) {
            int mlq = r*16 + rl;
            int p   = seg*sl + (qt*128 + mlq)*dr + off;
            float4 q = *(const float4*)(g_q + (baseBL + p)*512 + h*64 + f4);
            Qs[(f4+0)*QSTR + mlq] = q.x * SCALE;
            Qs[(f4+1)*QSTR + mlq] = q.y * SCALE;
            Qs[(f4+2)*QSTR + mlq] = q.z * SCALE;
            Qs[(f4+3)*QSTR + mlq] = q.w * SCALE;
        }
    }

    float m_i[8], l_i[8], acc[8][4];
    #pragma unroll
    for (int i = 0; i < 8; i++) {
        m_i[i] = -INFINITY; l_i[i] = 0.f;
        acc[i][0] = acc[i][1] = acc[i][2] = acc[i][3] = 0.f;
    }

    for (int kt = 0; kt < 16; kt++) {          // 1024 keys / 64
        __syncthreads();                        // prev PV done (also covers Q stores)
        // ---- load K,V tile (64 rows) ----
        {
            int f4 = (t & 15) << 2;
            int rl = t >> 4;
            #pragma unroll
            for (int r = 0; r < 4; r++) {
                int j = r*16 + rl;
                int p = seg*sl + (kt*64 + j)*dr + off;
                size_t gidx = (baseBL + p)*512 + h*64 + f4;
                float4 kv = *(const float4*)(g_k + gidx);
                Ks[(f4+0)*KSTR + j] = kv.x;
                Ks[(f4+1)*KSTR + j] = kv.y;
                Ks[(f4+2)*KSTR + j] = kv.z;
                Ks[(f4+3)*KSTR + j] = kv.w;
                *(float4*)(Vs + j*KSTR + f4) = *(const float4*)(g_v + gidx);
            }
        }
        __syncthreads();

        // ---- S = Q K^T (8x4 per thread) ----
        float s[8][4];
        #pragma unroll
        for (int i = 0; i < 8; i++)
            s[i][0] = s[i][1] = s[i][2] = s[i][3] = 0.f;

        #pragma unroll
        for (int kk = 0; kk < 64; kk++) {
            float4 qa = *(const float4*)(Qs + kk*QSTR + ty*8);
            float4 qb = *(const float4*)(Qs + kk*QSTR + ty*8 + 4);
            float4 kv = *(const float4*)(Ks + kk*KSTR + tx*4);
            float qv[8] = {qa.x,qa.y,qa.z,qa.w,qb.x,qb.y,qb.z,qb.w};
            #pragma unroll
            for (int i = 0; i < 8; i++) {
                s[i][0] += qv[i]*kv.x; s[i][1] += qv[i]*kv.y;
                s[i][2] += qv[i]*kv.z; s[i][3] += qv[i]*kv.w;
            }
        }

        // ---- online softmax (row stats across 16 tx lanes) ----
        #pragma unroll
        for (int i = 0; i < 8; i++) {
            float tm = fmaxf(fmaxf(s[i][0], s[i][1]), fmaxf(s[i][2], s[i][3]));
            #pragma unroll
            for (int o = 8; o >= 1; o >>= 1)
                tm = fmaxf(tm, __shfl_xor_sync(0xffffffffu, tm, o));
            float nm    = fmaxf(m_i[i], tm);
            float alpha = __expf(m_i[i] - nm);
            m_i[i] = nm;
            float rs = 0.f;
            #pragma unroll
            for (int j = 0; j < 4; j++) {
                s[i][j] = __expf(s[i][j] - nm);
                rs += s[i][j];
            }
            #pragma unroll
            for (int o = 8; o >= 1; o >>= 1)
                rs += __shfl_xor_sync(0xffffffffu, rs, o);
            l_i[i] = l_i[i]*alpha + rs;
            acc[i][0] *= alpha; acc[i][1] *= alpha;
            acc[i][2] *= alpha; acc[i][3] *= alpha;
            *(float4*)(Ps + (ty*8+i)*KSTR + tx*4) =
                make_float4(s[i][0], s[i][1], s[i][2], s[i][3]);
        }
        __syncthreads();

        // ---- O += P V (8 rows x 4 d-cols per thread) ----
        #pragma unroll
        for (int n4 = 0; n4 < 16; n4++) {
            float4 v0 = *(const float4*)(Vs + (n4*4+0)*KSTR + tx*4);
            float4 v1 = *(const float4*)(Vs + (n4*4+1)*KSTR + tx*4);
            float4 v2 = *(const float4*)(Vs + (n4*4+2)*KSTR + tx*4);
            float4 v3 = *(const float4*)(Vs + (n4*4+3)*KSTR + tx*4);
            #pragma unroll
            for (int i = 0; i < 8; i++) {
                float4 pp = *(const float4*)(Ps + (ty*8+i)*KSTR + n4*4);
                acc[i][0] += pp.x*v0.x + pp.y*v1.x + pp.z*v2.x + pp.w*v3.x;
                acc[i][1] += pp.x*v0.y + pp.y*v1.y + pp.z*v2.y + pp.w*v3.y;
                acc[i][2] += pp.x*v0.z + pp.y*v1.z + pp.z*v2.z + pp.w*v3.z;
                acc[i][3] += pp.x*v0.w + pp.y*v1.w + pp.z*v2.w + pp.w*v3.w;
            }
        }
    }

    // ---- epilogue: scatter O and LSE to dense layout ----
    #pragma unroll
    for (int i = 0; i < 8; i++) {
        int mlq = ty*8 + i;
        int p   = seg*sl + (qt*128 + mlq)*dr + off;
        float inv = 1.f / l_i[i];
        *(float4*)(og + (baseBL + p)*512 + h*64 + tx*4) =
            make_float4(acc[i][0]*inv, acc[i][1]*inv, acc[i][2]*inv, acc[i][3]*inv);
        if (tx == 0) {
            float lse = m_i[i] + logf(l_i[i]);
            if (lse == 0.0f) lse = NEG_FILL;   // mirror reference's ld==0 replacement
            lg[(baseBL + p)*NH + h] = lse;
        }
    }
}

// =====================================================================
// Combine branches with analytic coverage predicates.
// =====================================================================
__global__ __launch_bounds__(256) void combine_kernel() {
    int idx4 = blockIdx.x * blockDim.x + threadIdx.x;   // over 2,097,152 float4s
    if (idx4 >= ML * DIMV / 4) return;
    int col4 = idx4 & 127;          // 512/4
    int row  = idx4 >> 7;           // b*L + p
    int h    = col4 >> 4;
    int p    = row & (LL - 1);
    int li   = row * NH + h;

    float l1 = g_l0[li];
    float l2 = ((p & 1) == (h >> 2)) ? g_l1[li] : NEG_FILL;
    float l3 = ((p & 3) == (h >> 1)) ? g_l2[li] : NEG_FILL;
    float mm = fmaxf(l1, fmaxf(l2, l3));
    float w1 = __expf(l1 - mm), w2 = __expf(l2 - mm), w3 = __expf(l3 - mm);
    float inv = 1.f / (w1 + w2 + w3);
    w1 *= inv; w2 *= inv; w3 *= inv;

    float4 a = ((const float4*)g_o0)[idx4];
    float4 b = ((const float4*)g_o1)[idx4];
    float4 c = ((const float4*)g_o2)[idx4];
    float4 o;
    o.x = w1*a.x + w2*b.x + w3*c.x;
    o.y = w1*a.y + w2*b.y + w3*c.y;
    o.z = w1*a.z + w2*b.z + w3*c.z;
    o.w = w1*a.w + w2*b.w + w3*c.w;
    ((float4*)g_comb)[idx4] = o;
}

// =====================================================================
extern "C" void kernel_launch(void* const* d_in, const int* in_sizes, int n_in,
                              void* d_out, int out_size) {
    (void)in_sizes; (void)n_in; (void)out_size;
    const float* query = (const float*)d_in[0];
    const float* key_  = (const float*)d_in[1];
    const float* value = (const float*)d_in[2];
    const float* Wq    = (const float*)d_in[3];
    const float* Wk    = (const float*)d_in[4];
    const float* Wv    = (const float*)d_in[5];
    const float* Wo    = (const float*)d_in[6];
    const float* bo    = (const float*)d_in[7];
    float* out = (float*)d_out;

    float *qp, *kp, *vp, *cp;
    cudaGetSymbolAddress((void**)&qp, g_q);
    cudaGetSymbolAddress((void**)&kp, g_k);
    cudaGetSymbolAddress((void**)&vp, g_v);
    cudaGetSymbolAddress((void**)&cp, g_comb);

    cudaFuncSetAttribute(attn_kernel,
                         cudaFuncAttributeMaxDynamicSharedMemorySize,
                         ATTN_SMEM_BYTES);

    dim3 gg(128, 4);   // 16384/128 x 512/128
    gemm_xt<<<gg, 256>>>(query, Wq, nullptr, qp);
    gemm_xt<<<gg, 256>>>(key_,  Wk, nullptr, kp);
    gemm_xt<<<gg, 256>>>(value, Wv, nullptr, vp);

    attn_kernel<<<1792, 256, ATTN_SMEM_BYTES>>>();

    combine_kernel<<<ML * DIMV / 4 / 256, 256>>>();

    gemm_xt<<<gg, 256>>>(cp, Wo, bo, out);
}

// round 4
// speedup vs baseline: 2.9418x; 2.9418x over previous
#include <cuda_runtime.h>
#include <cstdint>
#include <math.h>

#define BB 2
#define LL 8192
#define DIMV 512
#define NH 8
#define HD 64
#define SCALE 0.125f
#define NEG_FILL -100000000.0f
#define ML (BB*LL)

// ---------------- scratch ----------------
__device__ float g_q[ML*DIMV];
__device__ float g_k[ML*DIMV];
__device__ float g_v[ML*DIMV];
__device__ float g_o0[ML*DIMV];
__device__ float g_o1[ML*DIMV];
__device__ float g_o2[ML*DIMV];
__device__ float g_l0[ML*NH];
__device__ float g_l1[ML*NH];
__device__ float g_l2[ML*NH];
__device__ float g_comb[ML*DIMV];

// ---------------- tf32 helpers ----------------
__device__ __forceinline__ uint32_t f2tf(float x) {
    uint32_t r;
    asm("cvt.rna.tf32.f32 %0, %1;" : "=r"(r) : "f"(x));
    return r;
}
__device__ __forceinline__ void mma8(float* c, const uint32_t* a, const uint32_t* b) {
    asm volatile(
        "mma.sync.aligned.m16n8k8.row.col.f32.tf32.tf32.f32 "
        "{%0,%1,%2,%3}, {%4,%5,%6,%7}, {%8,%9}, {%0,%1,%2,%3};"
        : "+f"(c[0]), "+f"(c[1]), "+f"(c[2]), "+f"(c[3])
        : "r"(a[0]), "r"(a[1]), "r"(a[2]), "r"(a[3]), "r"(b[0]), "r"(b[1]));
}

// =====================================================================
// tf32 mma GEMM: C[16384,512] = A[16384,512] @ W[512,512]^T (+bias)
// CTA 128x128, 256 thr, warp grid 2x4 (warp tile 64x32), BK=32,
// pad-36 smem rows (bank = 4g+t, conflict-free fragment loads),
// register prefetch of next chunk overlaps gmem latency with mma.
// =====================================================================
#define GPAD 36
__global__ __launch_bounds__(256) void gemm_mma(const float* __restrict__ A,
                                                const float* __restrict__ W,
                                                const float* __restrict__ bias,
                                                float* __restrict__ C) {
    __shared__ uint32_t sm[2 * 128 * GPAD];     // 36864 B
    uint32_t* As = sm;
    uint32_t* Ws = sm + 128 * GPAD;
    const int t = threadIdx.x, lane = t & 31, w = t >> 5;
    const int g = lane >> 2, tg = lane & 3;
    const int m0 = blockIdx.x * 128, n0 = blockIdx.y * 128;
    const int wm = (w >> 2) * 64, wn = (w & 3) * 32;

    float c[4][4][4];
    #pragma unroll
    for (int i = 0; i < 4; i++)
        #pragma unroll
        for (int j = 0; j < 4; j++)
            #pragma unroll
            for (int q = 0; q < 4; q++) c[i][j][q] = 0.f;

    float4 pa[4], pw[4];
    #pragma unroll
    for (int r = 0; r < 4; r++) {
        int idx = t + r * 256, row = idx >> 3, c4 = idx & 7;
        pa[r] = *(const float4*)(A + (size_t)(m0 + row) * 512 + c4 * 4);
        pw[r] = *(const float4*)(W + (size_t)(n0 + row) * 512 + c4 * 4);
    }

    for (int ck = 0; ck < 16; ck++) {
        #pragma unroll
        for (int r = 0; r < 4; r++) {
            int idx = t + r * 256, row = idx >> 3, c4 = idx & 7;
            int base = row * GPAD + c4 * 4;
            As[base+0] = f2tf(pa[r].x); As[base+1] = f2tf(pa[r].y);
            As[base+2] = f2tf(pa[r].z); As[base+3] = f2tf(pa[r].w);
            Ws[base+0] = f2tf(pw[r].x); Ws[base+1] = f2tf(pw[r].y);
            Ws[base+2] = f2tf(pw[r].z); Ws[base+3] = f2tf(pw[r].w);
        }
        __syncthreads();
        if (ck < 15) {
            int k0 = (ck + 1) * 32;
            #pragma unroll
            for (int r = 0; r < 4; r++) {
                int idx = t + r * 256, row = idx >> 3, c4 = idx & 7;
                pa[r] = *(const float4*)(A + (size_t)(m0 + row) * 512 + k0 + c4 * 4);
                pw[r] = *(const float4*)(W + (size_t)(n0 + row) * 512 + k0 + c4 * 4);
            }
        }
        #pragma unroll
        for (int ks = 0; ks < 4; ks++) {
            uint32_t af[4][4], bf[4][2];
            #pragma unroll
            for (int mt = 0; mt < 4; mt++) {
                int rb = wm + mt * 16;
                af[mt][0] = As[(rb + g)     * GPAD + ks*8 + tg];
                af[mt][1] = As[(rb + g + 8) * GPAD + ks*8 + tg];
                af[mt][2] = As[(rb + g)     * GPAD + ks*8 + tg + 4];
                af[mt][3] = As[(rb + g + 8) * GPAD + ks*8 + tg + 4];
            }
            #pragma unroll
            for (int nt = 0; nt < 4; nt++) {
                int cb = wn + nt * 8;
                bf[nt][0] = Ws[(cb + g) * GPAD + ks*8 + tg];
                bf[nt][1] = Ws[(cb + g) * GPAD + ks*8 + tg + 4];
            }
            #pragma unroll
            for (int mt = 0; mt < 4; mt++)
                #pragma unroll
                for (int nt = 0; nt < 4; nt++)
                    mma8(c[mt][nt], af[mt], bf[nt]);
        }
        __syncthreads();
    }

    #pragma unroll
    for (int mt = 0; mt < 4; mt++) {
        int row0 = m0 + wm + mt * 16 + g;
        #pragma unroll
        for (int nt = 0; nt < 4; nt++) {
            int col = n0 + wn + nt * 8 + 2 * tg;
            float b0 = 0.f, b1 = 0.f;
            if (bias) { b0 = bias[col]; b1 = bias[col + 1]; }
            float2 v0 = make_float2(c[mt][nt][0] + b0, c[mt][nt][1] + b1);
            float2 v1 = make_float2(c[mt][nt][2] + b0, c[mt][nt][3] + b1);
            *(float2*)(C + (size_t)row0 * 512 + col)       = v0;
            *(float2*)(C + (size_t)(row0 + 8) * 512 + col) = v1;
        }
    }
}

// =====================================================================
// tf32 mma flash attention (no-max softmax; O accumulates in regs).
// CTA: (branch,b,seg,h,qtile of 128) -> 1792 CTAs, 256 thr, 8 warps.
// Warp owns 16 q rows. 16 k-tiles of 64 keys.
// smem: Ks[64][68], Vs[64][68], Ps[128][68] (also Q staging) = 69632 B
// =====================================================================
#define APAD 68
#define A_KS 0
#define A_VS (64*APAD)
#define A_PS (128*APAD)
#define ATTN_SMEM_WORDS (128*APAD + 128*APAD)
#define ATTN_SMEM_BYTES (ATTN_SMEM_WORDS*4)   // 69632

__global__ __launch_bounds__(256) void attn_mma() {
    extern __shared__ uint32_t sma[];
    uint32_t* Ks = sma + A_KS;
    uint32_t* Vs = sma + A_VS;
    uint32_t* Ps = sma + A_PS;

    const int t = threadIdx.x, lane = t & 31, w = t >> 5;
    const int g = lane >> 2, tg = lane & 3;
    const int rb = w * 16;

    int bid = blockIdx.x;
    int br, rem;
    if (bid < 1024)      { br = 0; rem = bid; }
    else if (bid < 1536) { br = 1; rem = bid - 1024; }
    else                 { br = 2; rem = bid - 1536; }
    int sl, dr, nseg;
    if (br == 0)      { sl = 1024; dr = 1; nseg = 8; }
    else if (br == 1) { sl = 2048; dr = 2; nseg = 4; }
    else              { sl = 4096; dr = 4; nseg = 2; }
    int qt = rem & 7; rem >>= 3;
    int h  = rem & 7; rem >>= 3;
    int seg = rem % nseg;
    int b   = rem / nseg;
    int off = h / (NH / dr);
    float* og = (br == 0) ? g_o0 : (br == 1) ? g_o1 : g_o2;
    float* lg = (br == 0) ? g_l0 : (br == 1) ? g_l1 : g_l2;
    const size_t baseBL = (size_t)b * LL;

    // ---- stage Q (scaled, tf32) into Ps, then grab per-warp A-frags ----
    #pragma unroll
    for (int i = 0; i < 8; i++) {
        int idx = t + i * 256, row = idx >> 4, c4 = idx & 15;
        int p = seg * sl + (qt * 128 + row) * dr + off;
        float4 q = *(const float4*)(g_q + (baseBL + p) * 512 + h * 64 + c4 * 4);
        int base = row * APAD + c4 * 4;
        Ps[base+0] = f2tf(q.x * SCALE); Ps[base+1] = f2tf(q.y * SCALE);
        Ps[base+2] = f2tf(q.z * SCALE); Ps[base+3] = f2tf(q.w * SCALE);
    }
    __syncthreads();
    uint32_t qa[8][4];
    #pragma unroll
    for (int ks = 0; ks < 8; ks++) {
        qa[ks][0] = Ps[(rb + g)     * APAD + ks*8 + tg];
        qa[ks][1] = Ps[(rb + g + 8) * APAD + ks*8 + tg];
        qa[ks][2] = Ps[(rb + g)     * APAD + ks*8 + tg + 4];
        qa[ks][3] = Ps[(rb + g + 8) * APAD + ks*8 + tg + 4];
    }

    float oc[8][4];
    #pragma unroll
    for (int nt = 0; nt < 8; nt++)
        oc[nt][0] = oc[nt][1] = oc[nt][2] = oc[nt][3] = 0.f;
    float racc0 = 0.f, racc1 = 0.f;

    for (int kt = 0; kt < 16; kt++) {
        __syncthreads();       // prev tile's PV done reading Ks/Vs (and Q frags read, kt=0)
        #pragma unroll
        for (int i = 0; i < 4; i++) {
            int idx = t + i * 256, row = idx >> 4, c4 = idx & 15;
            int p = seg * sl + (kt * 64 + row) * dr + off;
            size_t gidx = (baseBL + p) * 512 + h * 64 + c4 * 4;
            float4 kv = *(const float4*)(g_k + gidx);
            float4 vv = *(const float4*)(g_v + gidx);
            int base = row * APAD + c4 * 4;
            Ks[base+0] = f2tf(kv.x); Ks[base+1] = f2tf(kv.y);
            Ks[base+2] = f2tf(kv.z); Ks[base+3] = f2tf(kv.w);
            Vs[base+0] = f2tf(vv.x); Vs[base+1] = f2tf(vv.y);
            Vs[base+2] = f2tf(vv.z); Vs[base+3] = f2tf(vv.w);
        }
        __syncthreads();

        // ---- S = Q K^T  (16 q rows x 64 keys per warp) ----
        float sc[8][4];
        #pragma unroll
        for (int nt = 0; nt < 8; nt++)
            sc[nt][0] = sc[nt][1] = sc[nt][2] = sc[nt][3] = 0.f;
        #pragma unroll
        for (int ks = 0; ks < 8; ks++) {
            #pragma unroll
            for (int nt = 0; nt < 8; nt++) {
                uint32_t bf[2];
                bf[0] = Ks[(nt*8 + g) * APAD + ks*8 + tg];
                bf[1] = Ks[(nt*8 + g) * APAD + ks*8 + tg + 4];
                mma8(sc[nt], qa[ks], bf);
            }
        }

        // ---- P = exp(S); accumulate row sums; store P (tf32) ----
        #pragma unroll
        for (int nt = 0; nt < 8; nt++) {
            float e0 = __expf(sc[nt][0]), e1 = __expf(sc[nt][1]);
            float e2 = __expf(sc[nt][2]), e3 = __expf(sc[nt][3]);
            racc0 += e0 + e1;
            racc1 += e2 + e3;
            int colb = nt * 8 + 2 * tg;
            uint2 u0 = make_uint2(f2tf(e0), f2tf(e1));
            uint2 u1 = make_uint2(f2tf(e2), f2tf(e3));
            *(uint2*)(Ps + (rb + g)     * APAD + colb) = u0;
            *(uint2*)(Ps + (rb + g + 8) * APAD + colb) = u1;
        }
        __syncwarp();   // P rows are warp-private

        // ---- O += P V ----
        #pragma unroll
        for (int ks = 0; ks < 8; ks++) {
            uint32_t pf[4];
            pf[0] = Ps[(rb + g)     * APAD + ks*8 + tg];
            pf[1] = Ps[(rb + g + 8) * APAD + ks*8 + tg];
            pf[2] = Ps[(rb + g)     * APAD + ks*8 + tg + 4];
            pf[3] = Ps[(rb + g + 8) * APAD + ks*8 + tg + 4];
            #pragma unroll
            for (int nt = 0; nt < 8; nt++) {
                uint32_t vb[2];
                vb[0] = Vs[(ks*8 + tg)     * APAD + nt*8 + g];
                vb[1] = Vs[(ks*8 + tg + 4) * APAD + nt*8 + g];
                mma8(oc[nt], pf, vb);
            }
        }
        __syncwarp();
    }

    // ---- reduce row sums over the 4 lanes of each group ----
    racc0 += __shfl_xor_sync(0xffffffffu, racc0, 1);
    racc0 += __shfl_xor_sync(0xffffffffu, racc0, 2);
    racc1 += __shfl_xor_sync(0xffffffffu, racc1, 1);
    racc1 += __shfl_xor_sync(0xffffffffu, racc1, 2);
    float inv0 = 1.f / racc0, inv1 = 1.f / racc1;

    int row0 = qt * 128 + rb + g;
    int p0 = seg * sl + row0 * dr + off;
    int p1 = seg * sl + (row0 + 8) * dr + off;
    float* op0 = og + (baseBL + p0) * 512 + h * 64;
    float* op1 = og + (baseBL + p1) * 512 + h * 64;
    #pragma unroll
    for (int nt = 0; nt < 8; nt++) {
        int colb = nt * 8 + 2 * tg;
        *(float2*)(op0 + colb) = make_float2(oc[nt][0] * inv0, oc[nt][1] * inv0);
        *(float2*)(op1 + colb) = make_float2(oc[nt][2] * inv1, oc[nt][3] * inv1);
    }
    if (tg == 0) {
        float lse0 = logf(racc0);
        float lse1 = logf(racc1);
        if (lse0 == 0.0f) lse0 = NEG_FILL;
        if (lse1 == 0.0f) lse1 = NEG_FILL;
        lg[(baseBL + p0) * NH + h] = lse0;
        lg[(baseBL + p1) * NH + h] = lse1;
    }
}

// =====================================================================
// Combine branches with analytic coverage predicates.
// =====================================================================
__global__ __launch_bounds__(256) void combine_kernel() {
    int idx4 = blockIdx.x * blockDim.x + threadIdx.x;
    if (idx4 >= ML * DIMV / 4) return;
    int col4 = idx4 & 127;
    int row  = idx4 >> 7;
    int h    = col4 >> 4;
    int p    = row & (LL - 1);
    int li   = row * NH + h;

    float l1 = g_l0[li];
    float l2 = ((p & 1) == (h >> 2)) ? g_l1[li] : NEG_FILL;
    float l3 = ((p & 3) == (h >> 1)) ? g_l2[li] : NEG_FILL;
    float mm = fmaxf(l1, fmaxf(l2, l3));
    float w1 = __expf(l1 - mm), w2 = __expf(l2 - mm), w3 = __expf(l3 - mm);
    float inv = 1.f / (w1 + w2 + w3);
    w1 *= inv; w2 *= inv; w3 *= inv;

    float4 a = ((const float4*)g_o0)[idx4];
    float4 b = ((const float4*)g_o1)[idx4];
    float4 c = ((const float4*)g_o2)[idx4];
    float4 o;
    o.x = w1*a.x + w2*b.x + w3*c.x;
    o.y = w1*a.y + w2*b.y + w3*c.y;
    o.z = w1*a.z + w2*b.z + w3*c.z;
    o.w = w1*a.w + w2*b.w + w3*c.w;
    ((float4*)g_comb)[idx4] = o;
}

// =====================================================================
extern "C" void kernel_launch(void* const* d_in, const int* in_sizes, int n_in,
                              void* d_out, int out_size) {
    (void)in_sizes; (void)n_in; (void)out_size;
    const float* query = (const float*)d_in[0];
    const float* key_  = (const float*)d_in[1];
    const float* value = (const float*)d_in[2];
    const float* Wq    = (const float*)d_in[3];
    const float* Wk    = (const float*)d_in[4];
    const float* Wv    = (const float*)d_in[5];
    const float* Wo    = (const float*)d_in[6];
    const float* bo    = (const float*)d_in[7];
    float* out = (float*)d_out;

    float *qp, *kp, *vp, *cp;
    cudaGetSymbolAddress((void**)&qp, g_q);
    cudaGetSymbolAddress((void**)&kp, g_k);
    cudaGetSymbolAddress((void**)&vp, g_v);
    cudaGetSymbolAddress((void**)&cp, g_comb);

    cudaFuncSetAttribute(attn_mma, cudaFuncAttributeMaxDynamicSharedMemorySize,
                         ATTN_SMEM_BYTES);

    dim3 gg(128, 4);
    gemm_mma<<<gg, 256>>>(query, Wq, nullptr, qp);
    gemm_mma<<<gg, 256>>>(key_,  Wk, nullptr, kp);
    gemm_mma<<<gg, 256>>>(value, Wv, nullptr, vp);

    attn_mma<<<1792, 256, ATTN_SMEM_BYTES>>>();

    combine_kernel<<<ML * DIMV / 4 / 256, 256>>>();

    gemm_mma<<<gg, 256>>>(cp, Wo, bo, out);
}

// round 5
// speedup vs baseline: 3.3603x; 1.1423x over previous
#include <cuda_runtime.h>
#include <cstdint>
#include <math.h>

#define BB 2
#define LL 8192
#define DIMV 512
#define NH 8
#define HD 64
#define SCALE 0.125f
#define NEG_FILL -100000000.0f
#define ML (BB*LL)

// ---------------- scratch ----------------
__device__ float g_q[ML*DIMV];
__device__ float g_k[ML*DIMV];
__device__ float g_v[ML*DIMV];
__device__ float g_o0[ML*DIMV];
__device__ float g_o1[ML*DIMV];
__device__ float g_o2[ML*DIMV];
__device__ float g_l0[ML*NH];
__device__ float g_l1[ML*NH];
__device__ float g_l2[ML*NH];
__device__ float g_comb[ML*DIMV];

// ---------------- helpers ----------------
__device__ __forceinline__ uint32_t f2tf(float x) {
    uint32_t r;
    asm("cvt.rna.tf32.f32 %0, %1;" : "=r"(r) : "f"(x));
    return r;
}
__device__ __forceinline__ void mma8(float* c, const uint32_t* a, const uint32_t* b) {
    asm volatile(
        "mma.sync.aligned.m16n8k8.row.col.f32.tf32.tf32.f32 "
        "{%0,%1,%2,%3}, {%4,%5,%6,%7}, {%8,%9}, {%0,%1,%2,%3};"
        : "+f"(c[0]), "+f"(c[1]), "+f"(c[2]), "+f"(c[3])
        : "r"(a[0]), "r"(a[1]), "r"(a[2]), "r"(a[3]), "r"(b[0]), "r"(b[1]));
}
__device__ __forceinline__ uint32_t smem_u32(const void* p) {
    uint32_t a;
    asm("{ .reg .u64 t; cvta.to.shared.u64 t, %1; cvt.u32.u64 %0, t; }" : "=r"(a) : "l"(p));
    return a;
}
__device__ __forceinline__ void cp16(uint32_t dst, const void* src) {
    asm volatile("cp.async.cg.shared.global [%0], [%1], 16;" :: "r"(dst), "l"(src));
}
#define CP_COMMIT() asm volatile("cp.async.commit_group;" ::: "memory")
#define CP_WAIT1()  asm volatile("cp.async.wait_group 1;" ::: "memory")
#define CP_WAIT0()  asm volatile("cp.async.wait_group 0;" ::: "memory")

// =====================================================================
// tf32 mma GEMM with cp.async double buffering.
// C[16384,512] = A @ W^T (+bias). CTA 128x128, 128 thr, 4 warps,
// warp tile 64x64 (mt4 x nt8). BK=32, 2-stage pipeline.
// =====================================================================
#define GST 36
#define GBUF (128*GST*2)            // words per stage (A+W)
#define G_SMEM_BYTES (2*GBUF*4)     // 73728

__device__ __forceinline__ void gemm_body(const float* __restrict__ A,
                                          const float* __restrict__ W,
                                          const float* __restrict__ bias,
                                          float* __restrict__ C,
                                          uint32_t* smg) {
    uint32_t sb = smem_u32(smg);
    const int t = threadIdx.x, lane = t & 31, w = t >> 5;
    const int g = lane >> 2, tg = lane & 3;
    const int m0 = blockIdx.x * 128, n0 = blockIdx.y * 128;
    const int wm = (w >> 1) * 64, wn = (w & 1) * 64;

    float c[4][8][4];
    #pragma unroll
    for (int i = 0; i < 4; i++)
        #pragma unroll
        for (int j = 0; j < 8; j++)
            #pragma unroll
            for (int q = 0; q < 4; q++) c[i][j][q] = 0.f;

    // fill stage: 1024 16B copies per matrix per chunk over 128 threads
    auto fill = [&](int ck, int buf) {
        #pragma unroll
        for (int r = 0; r < 8; r++) {
            int idx = t + r * 128;
            int row = idx >> 3, c4 = idx & 7;
            uint32_t dstA = sb + (uint32_t)(buf * GBUF + row * GST + c4 * 4) * 4u;
            cp16(dstA, A + (size_t)(m0 + row) * 512 + ck * 32 + c4 * 4);
            uint32_t dstW = sb + (uint32_t)(buf * GBUF + 128 * GST + row * GST + c4 * 4) * 4u;
            cp16(dstW, W + (size_t)(n0 + row) * 512 + ck * 32 + c4 * 4);
        }
        CP_COMMIT();
    };

    fill(0, 0);
    fill(1, 1);

    for (int ck = 0; ck < 16; ck++) {
        if (ck < 15) CP_WAIT1(); else CP_WAIT0();
        __syncthreads();
        const uint32_t* As = smg + (ck & 1) * GBUF;
        const uint32_t* Ws = As + 128 * GST;
        #pragma unroll
        for (int ks = 0; ks < 4; ks++) {
            uint32_t af[4][4], bf[8][2];
            #pragma unroll
            for (int mt = 0; mt < 4; mt++) {
                int rb = wm + mt * 16;
                af[mt][0] = f2tf(__uint_as_float(As[(rb + g)     * GST + ks*8 + tg]));
                af[mt][1] = f2tf(__uint_as_float(As[(rb + g + 8) * GST + ks*8 + tg]));
                af[mt][2] = f2tf(__uint_as_float(As[(rb + g)     * GST + ks*8 + tg + 4]));
                af[mt][3] = f2tf(__uint_as_float(As[(rb + g + 8) * GST + ks*8 + tg + 4]));
            }
            #pragma unroll
            for (int nt = 0; nt < 8; nt++) {
                int rw = wn + nt * 8 + g;
                bf[nt][0] = f2tf(__uint_as_float(Ws[rw * GST + ks*8 + tg]));
                bf[nt][1] = f2tf(__uint_as_float(Ws[rw * GST + ks*8 + tg + 4]));
            }
            #pragma unroll
            for (int mt = 0; mt < 4; mt++)
                #pragma unroll
                for (int nt = 0; nt < 8; nt++)
                    mma8(c[mt][nt], af[mt], bf[nt]);
        }
        __syncthreads();
        if (ck + 2 < 16) fill(ck + 2, ck & 1);
    }

    #pragma unroll
    for (int mt = 0; mt < 4; mt++) {
        int row0 = m0 + wm + mt * 16 + g;
        #pragma unroll
        for (int nt = 0; nt < 8; nt++) {
            int col = n0 + wn + nt * 8 + 2 * tg;
            float b0 = 0.f, b1 = 0.f;
            if (bias) { b0 = bias[col]; b1 = bias[col + 1]; }
            *(float2*)(C + (size_t)row0 * 512 + col) =
                make_float2(c[mt][nt][0] + b0, c[mt][nt][1] + b1);
            *(float2*)(C + (size_t)(row0 + 8) * 512 + col) =
                make_float2(c[mt][nt][2] + b0, c[mt][nt][3] + b1);
        }
    }
}

__global__ __launch_bounds__(128, 2) void gemm_proj(const float* __restrict__ q,
                                                    const float* __restrict__ k,
                                                    const float* __restrict__ v,
                                                    const float* __restrict__ Wq,
                                                    const float* __restrict__ Wk,
                                                    const float* __restrict__ Wv) {
    extern __shared__ uint32_t smg[];
    const float* A; const float* W; float* C;
    if (blockIdx.z == 0)      { A = q; W = Wq; C = g_q; }
    else if (blockIdx.z == 1) { A = k; W = Wk; C = g_k; }
    else                      { A = v; W = Wv; C = g_v; }
    gemm_body(A, W, nullptr, C, smg);
}

__global__ __launch_bounds__(128, 2) void gemm_out(const float* __restrict__ Wo,
                                                   const float* __restrict__ bo,
                                                   float* __restrict__ out) {
    extern __shared__ uint32_t smg[];
    gemm_body(g_comb, Wo, bo, out, smg);
}

// =====================================================================
// tf32 mma flash attention, register-heavy warp tiles.
// CTA: (branch,b,seg,h,qtile of 128) -> 1792 CTAs, 128 thr, 4 warps.
// Warp owns 32 q rows (mt=2); Q frags + O accum live in registers.
// 16 k-tiles of 64 keys, each processed in 2 halves of 32 keys.
// smem: Ks[64][68] + Vs[64][68] + per-warp P[32][40]  = 55296 B
// =====================================================================
#define AST 68
#define PST 40
#define A_SMEM_WORDS (128*AST + 4*32*PST)
#define A_SMEM_BYTES (A_SMEM_WORDS*4)   // 55296

__global__ __launch_bounds__(128, 2) void attn_mma() {
    extern __shared__ uint32_t sma[];
    uint32_t* Ks = sma;
    uint32_t* Vs = sma + 64 * AST;
    const int t = threadIdx.x, lane = t & 31, w = t >> 5;
    const int g = lane >> 2, tg = lane & 3;
    uint32_t* Pw = sma + 128 * AST + w * 32 * PST;

    int bid = blockIdx.x;
    int br, rem;
    if (bid < 1024)      { br = 0; rem = bid; }
    else if (bid < 1536) { br = 1; rem = bid - 1024; }
    else                 { br = 2; rem = bid - 1536; }
    int sl, dr, nseg;
    if (br == 0)      { sl = 1024; dr = 1; nseg = 8; }
    else if (br == 1) { sl = 2048; dr = 2; nseg = 4; }
    else              { sl = 4096; dr = 4; nseg = 2; }
    int qt = rem & 7; rem >>= 3;
    int h  = rem & 7; rem >>= 3;
    int seg = rem % nseg;
    int b   = rem / nseg;
    int off = h / (NH / dr);
    float* og = (br == 0) ? g_o0 : (br == 1) ? g_o1 : g_o2;
    float* lg = (br == 0) ? g_l0 : (br == 1) ? g_l1 : g_l2;
    const size_t baseBL = (size_t)b * LL;

    // ---- stage Q in two halves through Ks; each warp grabs its frags ----
    uint32_t qa[2][8][4];
    #pragma unroll
    for (int sh = 0; sh < 2; sh++) {
        __syncthreads();
        #pragma unroll
        for (int i = 0; i < 8; i++) {
            int idx = t + i * 128;
            int row = idx >> 4, c4 = idx & 15;
            int p = seg * sl + (qt * 128 + sh * 64 + row) * dr + off;
            float4 q = *(const float4*)(g_q + (baseBL + p) * 512 + h * 64 + c4 * 4);
            int base = row * AST + c4 * 4;
            Ks[base+0] = f2tf(q.x * SCALE); Ks[base+1] = f2tf(q.y * SCALE);
            Ks[base+2] = f2tf(q.z * SCALE); Ks[base+3] = f2tf(q.w * SCALE);
        }
        __syncthreads();
        if ((w >> 1) == sh) {
            int rl = (w & 1) * 32;
            #pragma unroll
            for (int mt = 0; mt < 2; mt++) {
                int rb = rl + mt * 16;
                #pragma unroll
                for (int ks = 0; ks < 8; ks++) {
                    qa[mt][ks][0] = Ks[(rb + g)     * AST + ks*8 + tg];
                    qa[mt][ks][1] = Ks[(rb + g + 8) * AST + ks*8 + tg];
                    qa[mt][ks][2] = Ks[(rb + g)     * AST + ks*8 + tg + 4];
                    qa[mt][ks][3] = Ks[(rb + g + 8) * AST + ks*8 + tg + 4];
                }
            }
        }
    }

    float oc[2][8][4];
    #pragma unroll
    for (int mt = 0; mt < 2; mt++)
        #pragma unroll
        for (int db = 0; db < 8; db++)
            oc[mt][db][0] = oc[mt][db][1] = oc[mt][db][2] = oc[mt][db][3] = 0.f;
    float racc[2][2] = {{0.f, 0.f}, {0.f, 0.f}};

    for (int kt = 0; kt < 16; kt++) {
        __syncthreads();    // all warps done reading Ks/Vs of previous tile
        #pragma unroll
        for (int i = 0; i < 8; i++) {
            int idx = t + i * 128;
            int row = idx >> 4, c4 = idx & 15;
            int p = seg * sl + (kt * 64 + row) * dr + off;
            size_t gidx = (baseBL + p) * 512 + h * 64 + c4 * 4;
            float4 kv = *(const float4*)(g_k + gidx);
            float4 vv = *(const float4*)(g_v + gidx);
            int base = row * AST + c4 * 4;
            Ks[base+0] = f2tf(kv.x); Ks[base+1] = f2tf(kv.y);
            Ks[base+2] = f2tf(kv.z); Ks[base+3] = f2tf(kv.w);
            Vs[base+0] = f2tf(vv.x); Vs[base+1] = f2tf(vv.y);
            Vs[base+2] = f2tf(vv.z); Vs[base+3] = f2tf(vv.w);
        }
        __syncthreads();

        #pragma unroll
        for (int kh = 0; kh < 2; kh++) {
            // ---- S = Q K^T over 32 keys (kb 0..3), 32 q rows (mt 0..1) ----
            float sc[2][4][4];
            #pragma unroll
            for (int mt = 0; mt < 2; mt++)
                #pragma unroll
                for (int kb = 0; kb < 4; kb++)
                    sc[mt][kb][0] = sc[mt][kb][1] = sc[mt][kb][2] = sc[mt][kb][3] = 0.f;
            #pragma unroll
            for (int ks = 0; ks < 8; ks++) {
                #pragma unroll
                for (int kb = 0; kb < 4; kb++) {
                    uint32_t bf[2];
                    int kr = (kh*32 + kb*8 + g) * AST + ks*8 + tg;
                    bf[0] = Ks[kr];
                    bf[1] = Ks[kr + 4];
                    mma8(sc[0][kb], qa[0][ks], bf);
                    mma8(sc[1][kb], qa[1][ks], bf);
                }
            }

            // ---- P = exp(S), row sums, store to per-warp P buffer ----
            #pragma unroll
            for (int mt = 0; mt < 2; mt++) {
                #pragma unroll
                for (int kb = 0; kb < 4; kb++) {
                    float e0 = __expf(sc[mt][kb][0]), e1 = __expf(sc[mt][kb][1]);
                    float e2 = __expf(sc[mt][kb][2]), e3 = __expf(sc[mt][kb][3]);
                    racc[mt][0] += e0 + e1;
                    racc[mt][1] += e2 + e3;
                    int cb = kb * 8 + 2 * tg;
                    *(uint2*)(Pw + (mt*16 + g)     * PST + cb) = make_uint2(f2tf(e0), f2tf(e1));
                    *(uint2*)(Pw + (mt*16 + g + 8) * PST + cb) = make_uint2(f2tf(e2), f2tf(e3));
                }
            }
            __syncwarp();

            // ---- O += P V over this key half ----
            #pragma unroll
            for (int ksp = 0; ksp < 4; ksp++) {
                uint32_t pf[2][4];
                #pragma unroll
                for (int mt = 0; mt < 2; mt++) {
                    pf[mt][0] = Pw[(mt*16 + g)     * PST + ksp*8 + tg];
                    pf[mt][1] = Pw[(mt*16 + g + 8) * PST + ksp*8 + tg];
                    pf[mt][2] = Pw[(mt*16 + g)     * PST + ksp*8 + tg + 4];
                    pf[mt][3] = Pw[(mt*16 + g + 8) * PST + ksp*8 + tg + 4];
                }
                #pragma unroll
                for (int db = 0; db < 8; db++) {
                    uint32_t vb[2];
                    int vr = (kh*32 + ksp*8 + tg) * AST + db*8 + g;
                    vb[0] = Vs[vr];
                    vb[1] = Vs[vr + 4 * AST];
                    mma8(oc[0][db], pf[0], vb);
                    mma8(oc[1][db], pf[1], vb);
                }
            }
            __syncwarp();
        }
    }

    // ---- reduce row sums across the quad (lanes sharing g) ----
    #pragma unroll
    for (int mt = 0; mt < 2; mt++)
        #pragma unroll
        for (int rs = 0; rs < 2; rs++) {
            float v = racc[mt][rs];
            v += __shfl_xor_sync(0xffffffffu, v, 1);
            v += __shfl_xor_sync(0xffffffffu, v, 2);
            racc[mt][rs] = v;
        }

    // ---- epilogue ----
    #pragma unroll
    for (int mt = 0; mt < 2; mt++) {
        #pragma unroll
        for (int rs = 0; rs < 2; rs++) {
            int qrow = qt * 128 + w * 32 + mt * 16 + g + rs * 8;
            int p = seg * sl + qrow * dr + off;
            float inv = 1.f / racc[mt][rs];
            float* op = og + (baseBL + p) * 512 + h * 64;
            #pragma unroll
            for (int db = 0; db < 8; db++) {
                *(float2*)(op + db * 8 + 2 * tg) =
                    make_float2(oc[mt][db][rs*2+0] * inv, oc[mt][db][rs*2+1] * inv);
            }
            if (tg == 0) {
                float lse = logf(racc[mt][rs]);
                if (lse == 0.0f) lse = NEG_FILL;
                lg[(baseBL + p) * NH + h] = lse;
            }
        }
    }
}

// =====================================================================
// Combine branches with analytic coverage predicates.
// =====================================================================
__global__ __launch_bounds__(256) void combine_kernel() {
    int idx4 = blockIdx.x * blockDim.x + threadIdx.x;
    if (idx4 >= ML * DIMV / 4) return;
    int col4 = idx4 & 127;
    int row  = idx4 >> 7;
    int h    = col4 >> 4;
    int p    = row & (LL - 1);
    int li   = row * NH + h;

    float l1 = g_l0[li];
    float l2 = ((p & 1) == (h >> 2)) ? g_l1[li] : NEG_FILL;
    float l3 = ((p & 3) == (h >> 1)) ? g_l2[li] : NEG_FILL;
    float mm = fmaxf(l1, fmaxf(l2, l3));
    float w1 = __expf(l1 - mm), w2 = __expf(l2 - mm), w3 = __expf(l3 - mm);
    float inv = 1.f / (w1 + w2 + w3);
    w1 *= inv; w2 *= inv; w3 *= inv;

    float4 a = ((const float4*)g_o0)[idx4];
    float4 b = ((const float4*)g_o1)[idx4];
    float4 c = ((const float4*)g_o2)[idx4];
    float4 o;
    o.x = w1*a.x + w2*b.x + w3*c.x;
    o.y = w1*a.y + w2*b.y + w3*c.y;
    o.z = w1*a.z + w2*b.z + w3*c.z;
    o.w = w1*a.w + w2*b.w + w3*c.w;
    ((float4*)g_comb)[idx4] = o;
}

// =====================================================================
extern "C" void kernel_launch(void* const* d_in, const int* in_sizes, int n_in,
                              void* d_out, int out_size) {
    (void)in_sizes; (void)n_in; (void)out_size;
    const float* query = (const float*)d_in[0];
    const float* key_  = (const float*)d_in[1];
    const float* value = (const float*)d_in[2];
    const float* Wq    = (const float*)d_in[3];
    const float* Wk    = (const float*)d_in[4];
    const float* Wv    = (const float*)d_in[5];
    const float* Wo    = (const float*)d_in[6];
    const float* bo    = (const float*)d_in[7];
    float* out = (float*)d_out;

    cudaFuncSetAttribute(gemm_proj, cudaFuncAttributeMaxDynamicSharedMemorySize, G_SMEM_BYTES);
    cudaFuncSetAttribute(gemm_out,  cudaFuncAttributeMaxDynamicSharedMemorySize, G_SMEM_BYTES);
    cudaFuncSetAttribute(attn_mma,  cudaFuncAttributeMaxDynamicSharedMemorySize, A_SMEM_BYTES);

    dim3 gp(128, 4, 3);
    gemm_proj<<<gp, 128, G_SMEM_BYTES>>>(query, key_, value, Wq, Wk, Wv);

    attn_mma<<<1792, 128, A_SMEM_BYTES>>>();

    combine_kernel<<<ML * DIMV / 4 / 256, 256>>>();

    dim3 go(128, 4);
    gemm_out<<<go, 128, G_SMEM_BYTES>>>(Wo, bo, out);
}

// round 6
// speedup vs baseline: 5.1747x; 1.5399x over previous
#include <cuda_runtime.h>
#include <cuda_fp16.h>
#include <cstdint>
#include <math.h>

#define BB 2
#define LL 8192
#define DIMV 512
#define NH 8
#define HD 64
#define SCALE 0.125f
#define NEG_FILL -100000000.0f
#define ML (BB*LL)

// ---------------- scratch ----------------
__device__ __align__(16) __half g_qh[ML*DIMV];
__device__ __align__(16) __half g_kh[ML*DIMV];
__device__ __align__(16) __half g_vh[ML*DIMV];
__device__ float g_o0[ML*DIMV];
__device__ float g_o1[ML*DIMV];
__device__ float g_o2[ML*DIMV];
__device__ float g_l0[ML*NH];
__device__ float g_l1[ML*NH];
__device__ float g_l2[ML*NH];
__device__ float g_comb[ML*DIMV];

// ---------------- helpers ----------------
__device__ __forceinline__ uint32_t packh2(float lo, float hi) {
    __half2 h = __floats2half2_rn(lo, hi);
    return *reinterpret_cast<uint32_t*>(&h);
}
__device__ __forceinline__ void mma16(float* c, const uint32_t* a, uint32_t b0, uint32_t b1) {
    asm volatile(
        "mma.sync.aligned.m16n8k16.row.col.f32.f16.f16.f32 "
        "{%0,%1,%2,%3}, {%4,%5,%6,%7}, {%8,%9}, {%0,%1,%2,%3};"
        : "+f"(c[0]), "+f"(c[1]), "+f"(c[2]), "+f"(c[3])
        : "r"(a[0]), "r"(a[1]), "r"(a[2]), "r"(a[3]), "r"(b0), "r"(b1));
}
__device__ __forceinline__ uint32_t smem_u32(const void* p) {
    uint32_t a;
    asm("{ .reg .u64 t; cvta.to.shared.u64 t, %1; cvt.u32.u64 %0, t; }" : "=r"(a) : "l"(p));
    return a;
}
__device__ __forceinline__ void cp16(uint32_t dst, const void* src) {
    asm volatile("cp.async.cg.shared.global [%0], [%1], 16;" :: "r"(dst), "l"(src));
}
#define CP_COMMIT() asm volatile("cp.async.commit_group;" ::: "memory")
#define CP_WAIT1()  asm volatile("cp.async.wait_group 1;" ::: "memory")
#define CP_WAIT0()  asm volatile("cp.async.wait_group 0;" ::: "memory")

// =====================================================================
// fp16-mma GEMM with cp.async double buffering (fp32 in smem, cvt@read).
// C[16384,512] = A @ W^T (+bias). CTA 128x128, 128 thr, 4 warps,
// warp tile 64x64 (mt4 x nt8). BK=32, 2-stage pipeline.
// =====================================================================
#define GST 36
#define GBUF (128*GST*2)
#define G_SMEM_BYTES (2*GBUF*4)     // 73728

template <bool OUT_HALF>
__device__ __forceinline__ void gemm_body(const float* __restrict__ A,
                                          const float* __restrict__ W,
                                          const float* __restrict__ bias,
                                          float* __restrict__ Cf,
                                          __half* __restrict__ Ch,
                                          float* smg) {
    uint32_t sb = smem_u32(smg);
    const int t = threadIdx.x, lane = t & 31, w = t >> 5;
    const int g = lane >> 2, tg = lane & 3;
    const int m0 = blockIdx.x * 128, n0 = blockIdx.y * 128;
    const int wm = (w >> 1) * 64, wn = (w & 1) * 64;

    float c[4][8][4];
    #pragma unroll
    for (int i = 0; i < 4; i++)
        #pragma unroll
        for (int j = 0; j < 8; j++)
            #pragma unroll
            for (int q = 0; q < 4; q++) c[i][j][q] = 0.f;

    auto fill = [&](int ck, int buf) {
        #pragma unroll
        for (int r = 0; r < 8; r++) {
            int idx = t + r * 128;
            int row = idx >> 3, c4 = idx & 7;
            uint32_t dstA = sb + (uint32_t)(buf * GBUF + row * GST + c4 * 4) * 4u;
            cp16(dstA, A + (size_t)(m0 + row) * 512 + ck * 32 + c4 * 4);
            uint32_t dstW = sb + (uint32_t)(buf * GBUF + 128 * GST + row * GST + c4 * 4) * 4u;
            cp16(dstW, W + (size_t)(n0 + row) * 512 + ck * 32 + c4 * 4);
        }
        CP_COMMIT();
    };

    fill(0, 0);
    fill(1, 1);

    for (int ck = 0; ck < 16; ck++) {
        if (ck < 15) CP_WAIT1(); else CP_WAIT0();
        __syncthreads();
        const float* As = smg + (ck & 1) * GBUF;
        const float* Ws = As + 128 * GST;
        #pragma unroll
        for (int ks = 0; ks < 2; ks++) {
            uint32_t af[4][4], bf[8][2];
            #pragma unroll
            for (int mt = 0; mt < 4; mt++) {
                int rb = wm + mt * 16;
                float2 x0 = *(const float2*)(As + (rb + g)     * GST + ks*16 + 2*tg);
                float2 x1 = *(const float2*)(As + (rb + g + 8) * GST + ks*16 + 2*tg);
                float2 x2 = *(const float2*)(As + (rb + g)     * GST + ks*16 + 2*tg + 8);
                float2 x3 = *(const float2*)(As + (rb + g + 8) * GST + ks*16 + 2*tg + 8);
                af[mt][0] = packh2(x0.x, x0.y);
                af[mt][1] = packh2(x1.x, x1.y);
                af[mt][2] = packh2(x2.x, x2.y);
                af[mt][3] = packh2(x3.x, x3.y);
            }
            #pragma unroll
            for (int nt = 0; nt < 8; nt++) {
                int rw = wn + nt * 8 + g;
                float2 y0 = *(const float2*)(Ws + rw * GST + ks*16 + 2*tg);
                float2 y1 = *(const float2*)(Ws + rw * GST + ks*16 + 2*tg + 8);
                bf[nt][0] = packh2(y0.x, y0.y);
                bf[nt][1] = packh2(y1.x, y1.y);
            }
            #pragma unroll
            for (int mt = 0; mt < 4; mt++)
                #pragma unroll
                for (int nt = 0; nt < 8; nt++)
                    mma16(c[mt][nt], af[mt], bf[nt][0], bf[nt][1]);
        }
        __syncthreads();
        if (ck + 2 < 16) fill(ck + 2, ck & 1);
    }

    #pragma unroll
    for (int mt = 0; mt < 4; mt++) {
        int row0 = m0 + wm + mt * 16 + g;
        #pragma unroll
        for (int nt = 0; nt < 8; nt++) {
            int col = n0 + wn + nt * 8 + 2 * tg;
            if (OUT_HALF) {
                *(__half2*)(Ch + (size_t)row0 * 512 + col) =
                    __floats2half2_rn(c[mt][nt][0], c[mt][nt][1]);
                *(__half2*)(Ch + (size_t)(row0 + 8) * 512 + col) =
                    __floats2half2_rn(c[mt][nt][2], c[mt][nt][3]);
            } else {
                float b0 = 0.f, b1 = 0.f;
                if (bias) { b0 = bias[col]; b1 = bias[col + 1]; }
                *(float2*)(Cf + (size_t)row0 * 512 + col) =
                    make_float2(c[mt][nt][0] + b0, c[mt][nt][1] + b1);
                *(float2*)(Cf + (size_t)(row0 + 8) * 512 + col) =
                    make_float2(c[mt][nt][2] + b0, c[mt][nt][3] + b1);
            }
        }
    }
}

__global__ __launch_bounds__(128, 2) void gemm_proj(const float* __restrict__ q,
                                                    const float* __restrict__ k,
                                                    const float* __restrict__ v,
                                                    const float* __restrict__ Wq,
                                                    const float* __restrict__ Wk,
                                                    const float* __restrict__ Wv) {
    extern __shared__ float smg[];
    const float* A; const float* W; __half* C;
    if (blockIdx.z == 0)      { A = q; W = Wq; C = g_qh; }
    else if (blockIdx.z == 1) { A = k; W = Wk; C = g_kh; }
    else                      { A = v; W = Wv; C = g_vh; }
    gemm_body<true>(A, W, nullptr, nullptr, C, smg);
}

__global__ __launch_bounds__(128, 2) void gemm_out(const float* __restrict__ Wo,
                                                   const float* __restrict__ bo,
                                                   float* __restrict__ out) {
    extern __shared__ float smg[];
    gemm_body<false>(g_comb, Wo, bo, out, nullptr, smg);
}

// =====================================================================
// fp16-mma flash attention, cp.async double-buffered K/V, no-max softmax.
// CTA: (branch,b,seg,h,qtile of 128) -> 1792 CTAs, 128 thr, 4 warps.
// Warp: 32 q rows; Q frags + O accum in registers. 16 k-tiles of 64 keys,
// each in 2 halves of 32. Smem (halves): 2x(K 64x72 + V 64x72) + P 4x32x40.
// =====================================================================
#define KSTH 72
#define PSTH 40
#define ABUF (64*KSTH)                 // 4608 halves per K or V tile
#define A_SMEM_BYTES ((4*ABUF + 4*32*PSTH)*2)   // 47104

__global__ __launch_bounds__(128, 2) void attn_mma() {
    extern __shared__ __half smh[];
    uint32_t sb = smem_u32(smh);
    const int t = threadIdx.x, lane = t & 31, w = t >> 5;
    const int g = lane >> 2, tg = lane & 3;
    __half* Pw = smh + 4*ABUF + w * 32 * PSTH;

    int bid = blockIdx.x;
    int br, rem;
    if (bid < 1024)      { br = 0; rem = bid; }
    else if (bid < 1536) { br = 1; rem = bid - 1024; }
    else                 { br = 2; rem = bid - 1536; }
    int sl, dr, nseg;
    if (br == 0)      { sl = 1024; dr = 1; nseg = 8; }
    else if (br == 1) { sl = 2048; dr = 2; nseg = 4; }
    else              { sl = 4096; dr = 4; nseg = 2; }
    int qt = rem & 7; rem >>= 3;
    int h  = rem & 7; rem >>= 3;
    int seg = rem % nseg;
    int b   = rem / nseg;
    int off = h / (NH / dr);
    float* og = (br == 0) ? g_o0 : (br == 1) ? g_o1 : g_o2;
    float* lg = (br == 0) ? g_l0 : (br == 1) ? g_l1 : g_l2;
    const size_t baseBL = (size_t)b * LL;

    // ---- stage Q (raw halves) into buffer-0 region via cp.async ----
    #pragma unroll
    for (int i = 0; i < 8; i++) {
        int idx = t + i * 128;
        int row = idx >> 3, c8 = idx & 7;
        int p = seg * sl + (qt * 128 + row) * dr + off;
        cp16(sb + (uint32_t)(row * KSTH + c8 * 8) * 2u,
             g_qh + (baseBL + p) * 512 + h * 64 + c8 * 8);
    }
    CP_COMMIT();
    CP_WAIT0();
    __syncthreads();

    // ---- extract Q fragments (warp owns rows w*32..w*32+31) ----
    uint32_t qa[2][4][4];
    {
        const __half* Qh = smh;
        int rl = w * 32;
        #pragma unroll
        for (int mt = 0; mt < 2; mt++) {
            int rb = rl + mt * 16;
            #pragma unroll
            for (int ks = 0; ks < 4; ks++) {
                qa[mt][ks][0] = *(const uint32_t*)(Qh + (rb + g)     * KSTH + ks*16 + 2*tg);
                qa[mt][ks][1] = *(const uint32_t*)(Qh + (rb + g + 8) * KSTH + ks*16 + 2*tg);
                qa[mt][ks][2] = *(const uint32_t*)(Qh + (rb + g)     * KSTH + ks*16 + 2*tg + 8);
                qa[mt][ks][3] = *(const uint32_t*)(Qh + (rb + g + 8) * KSTH + ks*16 + 2*tg + 8);
            }
        }
    }
    __syncthreads();

    auto fill = [&](int kt, int buf) {
        #pragma unroll
        for (int i = 0; i < 4; i++) {
            int idx = t + i * 128;
            int row = idx >> 3, c8 = idx & 7;
            int p = seg * sl + (kt * 64 + row) * dr + off;
            size_t gidx = (baseBL + p) * 512 + h * 64 + c8 * 8;
            uint32_t dK = sb + (uint32_t)(buf * 2 * ABUF + row * KSTH + c8 * 8) * 2u;
            cp16(dK, g_kh + gidx);
            cp16(dK + ABUF * 2u, g_vh + gidx);
        }
        CP_COMMIT();
    };

    float oc[2][8][4];
    #pragma unroll
    for (int mt = 0; mt < 2; mt++)
        #pragma unroll
        for (int db = 0; db < 8; db++)
            oc[mt][db][0] = oc[mt][db][1] = oc[mt][db][2] = oc[mt][db][3] = 0.f;
    float racc[2][2] = {{0.f, 0.f}, {0.f, 0.f}};

    fill(0, 0);

    for (int kt = 0; kt < 16; kt++) {
        if (kt < 15) { fill(kt + 1, (kt + 1) & 1); CP_WAIT1(); }
        else CP_WAIT0();
        __syncthreads();
        const __half* Kh = smh + (kt & 1) * 2 * ABUF;
        const __half* Vh = Kh + ABUF;

        #pragma unroll
        for (int kh = 0; kh < 2; kh++) {
            // ---- S = Q K^T over 32 keys ----
            float sc[2][4][4];
            #pragma unroll
            for (int mt = 0; mt < 2; mt++)
                #pragma unroll
                for (int kb = 0; kb < 4; kb++)
                    sc[mt][kb][0] = sc[mt][kb][1] = sc[mt][kb][2] = sc[mt][kb][3] = 0.f;
            #pragma unroll
            for (int ks = 0; ks < 4; ks++) {
                #pragma unroll
                for (int kb = 0; kb < 4; kb++) {
                    const __half* kp = Kh + (kh*32 + kb*8 + g) * KSTH + ks*16 + 2*tg;
                    uint32_t bf0 = *(const uint32_t*)kp;
                    uint32_t bf1 = *(const uint32_t*)(kp + 8);
                    mma16(sc[0][kb], qa[0][ks], bf0, bf1);
                    mma16(sc[1][kb], qa[1][ks], bf0, bf1);
                }
            }

            // ---- P = exp(S*SCALE); row sums; store half2 P ----
            #pragma unroll
            for (int mt = 0; mt < 2; mt++) {
                #pragma unroll
                for (int kb = 0; kb < 4; kb++) {
                    float e0 = __expf(sc[mt][kb][0] * SCALE);
                    float e1 = __expf(sc[mt][kb][1] * SCALE);
                    float e2 = __expf(sc[mt][kb][2] * SCALE);
                    float e3 = __expf(sc[mt][kb][3] * SCALE);
                    racc[mt][0] += e0 + e1;
                    racc[mt][1] += e2 + e3;
                    int cb = kb * 8 + 2 * tg;
                    *(uint32_t*)(Pw + (mt*16 + g)     * PSTH + cb) = packh2(e0, e1);
                    *(uint32_t*)(Pw + (mt*16 + g + 8) * PSTH + cb) = packh2(e2, e3);
                }
            }
            __syncwarp();

            // ---- O += P V over this 32-key half ----
            #pragma unroll
            for (int ksp = 0; ksp < 2; ksp++) {
                uint32_t pf[2][4];
                #pragma unroll
                for (int mt = 0; mt < 2; mt++) {
                    const __half* pp = Pw + (mt*16 + g) * PSTH + ksp*16 + 2*tg;
                    pf[mt][0] = *(const uint32_t*)pp;
                    pf[mt][1] = *(const uint32_t*)(pp + 8 * PSTH);
                    pf[mt][2] = *(const uint32_t*)(pp + 8);
                    pf[mt][3] = *(const uint32_t*)(pp + 8 * PSTH + 8);
                }
                int key0 = kh*32 + ksp*16 + 2*tg;
                #pragma unroll
                for (int db = 0; db < 8; db++) {
                    int d = db * 8 + g;
                    const __half* vp = Vh + key0 * KSTH + d;
                    __half2 v0h, v1h;
                    v0h.x = vp[0];        v0h.y = vp[KSTH];
                    v1h.x = vp[8*KSTH];   v1h.y = vp[9*KSTH];
                    uint32_t vb0 = *(uint32_t*)&v0h;
                    uint32_t vb1 = *(uint32_t*)&v1h;
                    mma16(oc[0][db], pf[0], vb0, vb1);
                    mma16(oc[1][db], pf[1], vb0, vb1);
                }
            }
            __syncwarp();
        }
        __syncthreads();
    }

    // ---- reduce row sums across the quad ----
    #pragma unroll
    for (int mt = 0; mt < 2; mt++)
        #pragma unroll
        for (int rs = 0; rs < 2; rs++) {
            float v = racc[mt][rs];
            v += __shfl_xor_sync(0xffffffffu, v, 1);
            v += __shfl_xor_sync(0xffffffffu, v, 2);
            racc[mt][rs] = v;
        }

    // ---- epilogue ----
    #pragma unroll
    for (int mt = 0; mt < 2; mt++) {
        #pragma unroll
        for (int rs = 0; rs < 2; rs++) {
            int qrow = qt * 128 + w * 32 + mt * 16 + g + rs * 8;
            int p = seg * sl + qrow * dr + off;
            float inv = 1.f / racc[mt][rs];
            float* op = og + (baseBL + p) * 512 + h * 64;
            #pragma unroll
            for (int db = 0; db < 8; db++) {
                *(float2*)(op + db * 8 + 2 * tg) =
                    make_float2(oc[mt][db][rs*2+0] * inv, oc[mt][db][rs*2+1] * inv);
            }
            if (tg == 0) {
                float lse = logf(racc[mt][rs]);
                if (lse == 0.0f) lse = NEG_FILL;
                lg[(baseBL + p) * NH + h] = lse;
            }
        }
    }
}

// =====================================================================
// Combine branches with analytic coverage predicates.
// =====================================================================
__global__ __launch_bounds__(256) void combine_kernel() {
    int idx4 = blockIdx.x * blockDim.x + threadIdx.x;
    if (idx4 >= ML * DIMV / 4) return;
    int col4 = idx4 & 127;
    int row  = idx4 >> 7;
    int h    = col4 >> 4;
    int p    = row & (LL - 1);
    int li   = row * NH + h;

    float l1 = g_l0[li];
    float l2 = ((p & 1) == (h >> 2)) ? g_l1[li] : NEG_FILL;
    float l3 = ((p & 3) == (h >> 1)) ? g_l2[li] : NEG_FILL;
    float mm = fmaxf(l1, fmaxf(l2, l3));
    float w1 = __expf(l1 - mm), w2 = __expf(l2 - mm), w3 = __expf(l3 - mm);
    float inv = 1.f / (w1 + w2 + w3);
    w1 *= inv; w2 *= inv; w3 *= inv;

    float4 a = ((const float4*)g_o0)[idx4];
    float4 b = ((const float4*)g_o1)[idx4];
    float4 c = ((const float4*)g_o2)[idx4];
    float4 o;
    o.x = w1*a.x + w2*b.x + w3*c.x;
    o.y = w1*a.y + w2*b.y + w3*c.y;
    o.z = w1*a.z + w2*b.z + w3*c.z;
    o.w = w1*a.w + w2*b.w + w3*c.w;
    ((float4*)g_comb)[idx4] = o;
}

// =====================================================================
extern "C" void kernel_launch(void* const* d_in, const int* in_sizes, int n_in,
                              void* d_out, int out_size) {
    (void)in_sizes; (void)n_in; (void)out_size;
    const float* query = (const float*)d_in[0];
    const float* key_  = (const float*)d_in[1];
    const float* value = (const float*)d_in[2];
    const float* Wq    = (const float*)d_in[3];
    const float* Wk    = (const float*)d_in[4];
    const float* Wv    = (const float*)d_in[5];
    const float* Wo    = (const float*)d_in[6];
    const float* bo    = (const float*)d_in[7];
    float* out = (float*)d_out;

    cudaFuncSetAttribute(gemm_proj, cudaFuncAttributeMaxDynamicSharedMemorySize, G_SMEM_BYTES);
    cudaFuncSetAttribute(gemm_out,  cudaFuncAttributeMaxDynamicSharedMemorySize, G_SMEM_BYTES);
    cudaFuncSetAttribute(attn_mma,  cudaFuncAttributeMaxDynamicSharedMemorySize, A_SMEM_BYTES);

    dim3 gp(128, 4, 3);
    gemm_proj<<<gp, 128, G_SMEM_BYTES>>>(query, key_, value, Wq, Wk, Wv);

    attn_mma<<<1792, 128, A_SMEM_BYTES>>>();

    combine_kernel<<<ML * DIMV / 4 / 256, 256>>>();

    dim3 go(128, 4);
    gemm_out<<<go, 128, G_SMEM_BYTES>>>(Wo, bo, out);
}

// round 9
// speedup vs baseline: 5.5799x; 1.0783x over previous
#include <cuda_runtime.h>
#include <cuda_fp16.h>
#include <cstdint>
#include <math.h>

#define BB 2
#define LL 8192
#define DIMV 512
#define NH 8
#define HD 64
#define SCALE 0.125f
#define NEG_FILL -100000000.0f
#define ML (BB*LL)

// ---------------- scratch ----------------
__device__ __align__(16) __half g_qh[ML*DIMV];
__device__ __align__(16) __half g_kh[ML*DIMV];
__device__ __align__(16) __half g_vh[ML*DIMV];
__device__ float g_o0[ML*DIMV];
__device__ float g_o1[ML*DIMV];
__device__ float g_o2[ML*DIMV];
__device__ float g_l0[ML*NH];
__device__ float g_l1[ML*NH];
__device__ float g_l2[ML*NH];
__device__ float g_comb[ML*DIMV];

// ---------------- helpers ----------------
__device__ __forceinline__ uint32_t packh2(float lo, float hi) {
    __half2 h = __floats2half2_rn(lo, hi);
    return *reinterpret_cast<uint32_t*>(&h);
}
__device__ __forceinline__ void mma16(float* c, const uint32_t* a, uint32_t b0, uint32_t b1) {
    asm volatile(
        "mma.sync.aligned.m16n8k16.row.col.f32.f16.f16.f32 "
        "{%0,%1,%2,%3}, {%4,%5,%6,%7}, {%8,%9}, {%0,%1,%2,%3};"
        : "+f"(c[0]), "+f"(c[1]), "+f"(c[2]), "+f"(c[3])
        : "r"(a[0]), "r"(a[1]), "r"(a[2]), "r"(a[3]), "r"(b0), "r"(b1));
}
__device__ __forceinline__ uint32_t smem_u32(const void* p) {
    uint32_t a;
    asm("{ .reg .u64 t; cvta.to.shared.u64 t, %1; cvt.u32.u64 %0, t; }" : "=r"(a) : "l"(p));
    return a;
}
__device__ __forceinline__ void cp16(uint32_t dst, const void* src) {
    asm volatile("cp.async.cg.shared.global [%0], [%1], 16;" :: "r"(dst), "l"(src));
}
#define CP_COMMIT() asm volatile("cp.async.commit_group;" ::: "memory")
#define CP_WAIT1()  asm volatile("cp.async.wait_group 1;" ::: "memory")
#define CP_WAIT0()  asm volatile("cp.async.wait_group 0;" ::: "memory")

// exp(x*SCALE) with one mul + ex2  (SCALE * log2(e) = 0.125 * 1.4426950408889634)
__device__ __forceinline__ float expsc(float x) {
    float r;
    asm("ex2.approx.f32 %0, %1;" : "=f"(r) : "f"(x * 0.180336880f));
    return r;
}

// =====================================================================
// fp16-mma GEMM, cp.async double-buffered, 256 thr / 8 warps.
// C[16384,512] = A @ W^T (+bias). CTA 128x128, warp tile 64x32 (mt4 x nt4).
// GST=40 pad -> conflict-free float2 fragment loads.
// =====================================================================
#define GST 40
#define GBUF (128*GST*2)            // words per stage (A then W)
#define G_SMEM_BYTES (2*GBUF*4)     // 81920

template <bool OUT_HALF>
__device__ __forceinline__ void gemm_body(const float* __restrict__ A,
                                          const float* __restrict__ W,
                                          const float* __restrict__ bias,
                                          float* __restrict__ Cf,
                                          __half* __restrict__ Ch,
                                          float* smg) {
    uint32_t sb = smem_u32(smg);
    const int t = threadIdx.x, lane = t & 31, w = t >> 5;
    const int g = lane >> 2, tg = lane & 3;
    const int m0 = blockIdx.x * 128, n0 = blockIdx.y * 128;
    const int wm = (w >> 2) * 64, wn = (w & 3) * 32;

    float c[4][4][4];
    #pragma unroll
    for (int i = 0; i < 4; i++)
        #pragma unroll
        for (int j = 0; j < 4; j++)
            #pragma unroll
            for (int q = 0; q < 4; q++) c[i][j][q] = 0.f;

    auto fill = [&](int ck, int buf) {
        #pragma unroll
        for (int r = 0; r < 4; r++) {
            int idx = t + r * 256;
            int row = idx >> 3, c4 = idx & 7;
            uint32_t dstA = sb + (uint32_t)(buf * GBUF + row * GST + c4 * 4) * 4u;
            cp16(dstA, A + (size_t)(m0 + row) * 512 + ck * 32 + c4 * 4);
            uint32_t dstW = sb + (uint32_t)(buf * GBUF + 128 * GST + row * GST + c4 * 4) * 4u;
            cp16(dstW, W + (size_t)(n0 + row) * 512 + ck * 32 + c4 * 4);
        }
        CP_COMMIT();
    };

    fill(0, 0);
    fill(1, 1);

    for (int ck = 0; ck < 16; ck++) {
        if (ck < 15) CP_WAIT1(); else CP_WAIT0();
        __syncthreads();
        const float* As = smg + (ck & 1) * GBUF;
        const float* Ws = As + 128 * GST;
        #pragma unroll
        for (int ks = 0; ks < 2; ks++) {
            uint32_t af[4][4], bf[4][2];
            #pragma unroll
            for (int mt = 0; mt < 4; mt++) {
                int rb = wm + mt * 16;
                float2 x0 = *(const float2*)(As + (rb + g)     * GST + ks*16 + 2*tg);
                float2 x1 = *(const float2*)(As + (rb + g + 8) * GST + ks*16 + 2*tg);
                float2 x2 = *(const float2*)(As + (rb + g)     * GST + ks*16 + 2*tg + 8);
                float2 x3 = *(const float2*)(As + (rb + g + 8) * GST + ks*16 + 2*tg + 8);
                af[mt][0] = packh2(x0.x, x0.y);
                af[mt][1] = packh2(x1.x, x1.y);
                af[mt][2] = packh2(x2.x, x2.y);
                af[mt][3] = packh2(x3.x, x3.y);
            }
            #pragma unroll
            for (int nt = 0; nt < 4; nt++) {
                int rw = wn + nt * 8 + g;
                float2 y0 = *(const float2*)(Ws + rw * GST + ks*16 + 2*tg);
                float2 y1 = *(const float2*)(Ws + rw * GST + ks*16 + 2*tg + 8);
                bf[nt][0] = packh2(y0.x, y0.y);
                bf[nt][1] = packh2(y1.x, y1.y);
            }
            #pragma unroll
            for (int mt = 0; mt < 4; mt++)
                #pragma unroll
                for (int nt = 0; nt < 4; nt++)
                    mma16(c[mt][nt], af[mt], bf[nt][0], bf[nt][1]);
        }
        __syncthreads();
        if (ck + 2 < 16) fill(ck + 2, ck & 1);
    }

    #pragma unroll
    for (int mt = 0; mt < 4; mt++) {
        int row0 = m0 + wm + mt * 16 + g;
        #pragma unroll
        for (int nt = 0; nt < 4; nt++) {
            int col = n0 + wn + nt * 8 + 2 * tg;
            if (OUT_HALF) {
                *(__half2*)(Ch + (size_t)row0 * 512 + col) =
                    __floats2half2_rn(c[mt][nt][0], c[mt][nt][1]);
                *(__half2*)(Ch + (size_t)(row0 + 8) * 512 + col) =
                    __floats2half2_rn(c[mt][nt][2], c[mt][nt][3]);
            } else {
                float b0 = 0.f, b1 = 0.f;
                if (bias) { b0 = bias[col]; b1 = bias[col + 1]; }
                *(float2*)(Cf + (size_t)row0 * 512 + col) =
                    make_float2(c[mt][nt][0] + b0, c[mt][nt][1] + b1);
                *(float2*)(Cf + (size_t)(row0 + 8) * 512 + col) =
                    make_float2(c[mt][nt][2] + b0, c[mt][nt][3] + b1);
            }
        }
    }
}

__global__ __launch_bounds__(256, 2) void gemm_proj(const float* __restrict__ q,
                                                    const float* __restrict__ k,
                                                    const float* __restrict__ v,
                                                    const float* __restrict__ Wq,
                                                    const float* __restrict__ Wk,
                                                    const float* __restrict__ Wv) {
    extern __shared__ float smg[];
    const float* A; const float* W; __half* C;
    if (blockIdx.z == 0)      { A = q; W = Wq; C = g_qh; }
    else if (blockIdx.z == 1) { A = k; W = Wk; C = g_kh; }
    else                      { A = v; W = Wv; C = g_vh; }
    gemm_body<true>(A, W, nullptr, nullptr, C, smg);
}

__global__ __launch_bounds__(256, 2) void gemm_out(const float* __restrict__ Wo,
                                                   const float* __restrict__ bo,
                                                   float* __restrict__ out) {
    extern __shared__ float smg[];
    gemm_body<false>(g_comb, Wo, bo, out, nullptr, smg);
}

// =====================================================================
// fp16-mma flash attention. CTA = 256 q rows (2 q-tiles) of one
// (branch,b,seg,h) block -> 896 CTAs, 256 thr, 8 warps.
// Warp: 32 q rows; Q frags + O accum in regs. 16 k-tiles of 64 keys,
// cp.async double-buffered.
// smem: KV 2x(K 64x72 + V 64x72) + P 8x32x40 = 57344 B
// =====================================================================
#define KSTH 72
#define PSTH 40
#define ABUF (64*KSTH)                 // 4608 halves per 64-row tile
#define A_SMEM_BYTES ((4*ABUF + 8*32*PSTH)*2)   // 57344

__global__ __launch_bounds__(256, 1) void attn_mma() {
    extern __shared__ __half smh[];
    uint32_t sb = smem_u32(smh);
    const int t = threadIdx.x, lane = t & 31, w = t >> 5;
    const int g = lane >> 2, tg = lane & 3;
    __half* Pw = smh + 4*ABUF + w * 32 * PSTH;

    int bid = blockIdx.x;
    int br, rem;
    if (bid < 512)      { br = 0; rem = bid; }
    else if (bid < 768) { br = 1; rem = bid - 512; }
    else                { br = 2; rem = bid - 768; }
    int sl, dr, nseg;
    if (br == 0)      { sl = 1024; dr = 1; nseg = 8; }
    else if (br == 1) { sl = 2048; dr = 2; nseg = 4; }
    else              { sl = 4096; dr = 4; nseg = 2; }
    int qs = rem & 3; rem >>= 2;
    int h  = rem & 7; rem >>= 3;
    int seg = rem % nseg;
    int b   = rem / nseg;
    int off = h / (NH / dr);
    float* og = (br == 0) ? g_o0 : (br == 1) ? g_o1 : g_o2;
    float* lg = (br == 0) ? g_l0 : (br == 1) ? g_l1 : g_l2;
    const size_t baseBL = (size_t)b * LL;

    // ---- stage all 256 Q rows (halves) across the 4 KV regions ----
    #pragma unroll
    for (int i = 0; i < 8; i++) {
        int idx = t + i * 256;
        int row = idx >> 3, c8 = idx & 7;
        int p = seg * sl + (qs * 256 + row) * dr + off;
        cp16(sb + (uint32_t)(row * KSTH + c8 * 8) * 2u,
             g_qh + (baseBL + p) * 512 + h * 64 + c8 * 8);
    }
    CP_COMMIT();
    CP_WAIT0();
    __syncthreads();

    // ---- extract Q fragments (warp owns rows w*32 .. w*32+31) ----
    uint32_t qa[2][4][4];
    {
        const __half* Qh = smh;
        int rl = w * 32;
        #pragma unroll
        for (int mt = 0; mt < 2; mt++) {
            int rb = rl + mt * 16;
            #pragma unroll
            for (int ks = 0; ks < 4; ks++) {
                qa[mt][ks][0] = *(const uint32_t*)(Qh + (rb + g)     * KSTH + ks*16 + 2*tg);
                qa[mt][ks][1] = *(const uint32_t*)(Qh + (rb + g + 8) * KSTH + ks*16 + 2*tg);
                qa[mt][ks][2] = *(const uint32_t*)(Qh + (rb + g)     * KSTH + ks*16 + 2*tg + 8);
                qa[mt][ks][3] = *(const uint32_t*)(Qh + (rb + g + 8) * KSTH + ks*16 + 2*tg + 8);
            }
        }
    }
    __syncthreads();

    auto fill = [&](int kt, int buf) {
        #pragma unroll
        for (int i = 0; i < 2; i++) {
            int idx = t + i * 256;
            int row = idx >> 3, c8 = idx & 7;
            int p = seg * sl + (kt * 64 + row) * dr + off;
            size_t gidx = (baseBL + p) * 512 + h * 64 + c8 * 8;
            uint32_t dK = sb + (uint32_t)(buf * 2 * ABUF + row * KSTH + c8 * 8) * 2u;
            cp16(dK, g_kh + gidx);
            cp16(dK + ABUF * 2u, g_vh + gidx);
        }
        CP_COMMIT();
    };

    float oc[2][8][4];
    #pragma unroll
    for (int mt = 0; mt < 2; mt++)
        #pragma unroll
        for (int db = 0; db < 8; db++)
            oc[mt][db][0] = oc[mt][db][1] = oc[mt][db][2] = oc[mt][db][3] = 0.f;
    float racc[2][2] = {{0.f, 0.f}, {0.f, 0.f}};

    fill(0, 0);

    for (int kt = 0; kt < 16; kt++) {
        if (kt < 15) { fill(kt + 1, (kt + 1) & 1); CP_WAIT1(); }
        else CP_WAIT0();
        __syncthreads();
        const __half* Kh = smh + (kt & 1) * 2 * ABUF;
        const __half* Vh = Kh + ABUF;

        #pragma unroll
        for (int kh = 0; kh < 2; kh++) {
            // ---- S = Q K^T over 32 keys ----
            float sc[2][4][4];
            #pragma unroll
            for (int mt = 0; mt < 2; mt++)
                #pragma unroll
                for (int kb = 0; kb < 4; kb++)
                    sc[mt][kb][0] = sc[mt][kb][1] = sc[mt][kb][2] = sc[mt][kb][3] = 0.f;
            #pragma unroll
            for (int ks = 0; ks < 4; ks++) {
                #pragma unroll
                for (int kb = 0; kb < 4; kb++) {
                    const __half* kp = Kh + (kh*32 + kb*8 + g) * KSTH + ks*16 + 2*tg;
                    uint32_t bf0 = *(const uint32_t*)kp;
                    uint32_t bf1 = *(const uint32_t*)(kp + 8);
                    mma16(sc[0][kb], qa[0][ks], bf0, bf1);
                    mma16(sc[1][kb], qa[1][ks], bf0, bf1);
                }
            }

            // ---- P = exp(S*SCALE); row sums; store half2 P ----
            #pragma unroll
            for (int mt = 0; mt < 2; mt++) {
                #pragma unroll
                for (int kb = 0; kb < 4; kb++) {
                    float e0 = expsc(sc[mt][kb][0]);
                    float e1 = expsc(sc[mt][kb][1]);
                    float e2 = expsc(sc[mt][kb][2]);
                    float e3 = expsc(sc[mt][kb][3]);
                    racc[mt][0] += e0 + e1;
                    racc[mt][1] += e2 + e3;
                    int cb = kb * 8 + 2 * tg;
                    *(uint32_t*)(Pw + (mt*16 + g)     * PSTH + cb) = packh2(e0, e1);
                    *(uint32_t*)(Pw + (mt*16 + g + 8) * PSTH + cb) = packh2(e2, e3);
                }
            }
            __syncwarp();

            // ---- O += P V over this 32-key half ----
            #pragma unroll
            for (int ksp = 0; ksp < 2; ksp++) {
                uint32_t pf[2][4];
                #pragma unroll
                for (int mt = 0; mt < 2; mt++) {
                    const __half* pp = Pw + (mt*16 + g) * PSTH + ksp*16 + 2*tg;
                    pf[mt][0] = *(const uint32_t*)pp;
                    pf[mt][1] = *(const uint32_t*)(pp + 8 * PSTH);
                    pf[mt][2] = *(const uint32_t*)(pp + 8);
                    pf[mt][3] = *(const uint32_t*)(pp + 8 * PSTH + 8);
                }
                int key0 = kh*32 + ksp*16 + 2*tg;
                #pragma unroll
                for (int db = 0; db < 8; db++) {
                    int d = db * 8 + g;
                    const __half* vp = Vh + key0 * KSTH + d;
                    __half2 v0h, v1h;
                    v0h.x = vp[0];        v0h.y = vp[KSTH];
                    v1h.x = vp[8*KSTH];   v1h.y = vp[9*KSTH];
                    uint32_t vb0 = *(uint32_t*)&v0h;
                    uint32_t vb1 = *(uint32_t*)&v1h;
                    mma16(oc[0][db], pf[0], vb0, vb1);
                    mma16(oc[1][db], pf[1], vb0, vb1);
                }
            }
            __syncwarp();
        }
        __syncthreads();
    }

    // ---- reduce row sums across the quad ----
    #pragma unroll
    for (int mt = 0; mt < 2; mt++)
        #pragma unroll
        for (int rs = 0; rs < 2; rs++) {
            float v = racc[mt][rs];
            v += __shfl_xor_sync(0xffffffffu, v, 1);
            v += __shfl_xor_sync(0xffffffffu, v, 2);
            racc[mt][rs] = v;
        }

    // ---- epilogue ----
    #pragma unroll
    for (int mt = 0; mt < 2; mt++) {
        #pragma unroll
        for (int rs = 0; rs < 2; rs++) {
            int qrow = qs * 256 + w * 32 + mt * 16 + g + rs * 8;
            int p = seg * sl + qrow * dr + off;
            float inv = 1.f / racc[mt][rs];
            float* op = og + (baseBL + p) * 512 + h * 64;
            #pragma unroll
            for (int db = 0; db < 8; db++) {
                *(float2*)(op + db * 8 + 2 * tg) =
                    make_float2(oc[mt][db][rs*2+0] * inv, oc[mt][db][rs*2+1] * inv);
            }
            if (tg == 0) {
                float lse = logf(racc[mt][rs]);
                if (lse == 0.0f) lse = NEG_FILL;
                lg[(baseBL + p) * NH + h] = lse;
            }
        }
    }
}

// =====================================================================
// Combine branches with analytic coverage predicates.
// =====================================================================
__global__ __launch_bounds__(256) void combine_kernel() {
    int idx4 = blockIdx.x * blockDim.x + threadIdx.x;
    if (idx4 >= ML * DIMV / 4) return;
    int col4 = idx4 & 127;
    int row  = idx4 >> 7;
    int h    = col4 >> 4;
    int p    = row & (LL - 1);
    int li   = row * NH + h;

    float l1 = g_l0[li];
    float l2 = ((p & 1) == (h >> 2)) ? g_l1[li] : NEG_FILL;
    float l3 = ((p & 3) == (h >> 1)) ? g_l2[li] : NEG_FILL;
    float mm = fmaxf(l1, fmaxf(l2, l3));
    float w1 = __expf(l1 - mm), w2 = __expf(l2 - mm), w3 = __expf(l3 - mm);
    float inv = 1.f / (w1 + w2 + w3);
    w1 *= inv; w2 *= inv; w3 *= inv;

    float4 a = ((const float4*)g_o0)[idx4];
    float4 b = ((const float4*)g_o1)[idx4];
    float4 c = ((const float4*)g_o2)[idx4];
    float4 o;
    o.x = w1*a.x + w2*b.x + w3*c.x;
    o.y = w1*a.y + w2*b.y + w3*c.y;
    o.z = w1*a.z + w2*b.z + w3*c.z;
    o.w = w1*a.w + w2*b.w + w3*c.w;
    ((float4*)g_comb)[idx4] = o;
}

// =====================================================================
extern "C" void kernel_launch(void* const* d_in, const int* in_sizes, int n_in,
                              void* d_out, int out_size) {
    (void)in_sizes; (void)n_in; (void)out_size;
    const float* query = (const float*)d_in[0];
    const float* key_  = (const float*)d_in[1];
    const float* value = (const float*)d_in[2];
    const float* Wq    = (const float*)d_in[3];
    const float* Wk    = (const float*)d_in[4];
    const float* Wv    = (const float*)d_in[5];
    const float* Wo    = (const float*)d_in[6];
    const float* bo    = (const float*)d_in[7];
    float* out = (float*)d_out;

    cudaFuncSetAttribute(gemm_proj, cudaFuncAttributeMaxDynamicSharedMemorySize, G_SMEM_BYTES);
    cudaFuncSetAttribute(gemm_out,  cudaFuncAttributeMaxDynamicSharedMemorySize, G_SMEM_BYTES);
    cudaFuncSetAttribute(attn_mma,  cudaFuncAttributeMaxDynamicSharedMemorySize, A_SMEM_BYTES);

    dim3 gp(128, 4, 3);
    gemm_proj<<<gp, 256, G_SMEM_BYTES>>>(query, key_, value, Wq, Wk, Wv);

    attn_mma<<<896, 256, A_SMEM_BYTES>>>();

    combine_kernel<<<ML * DIMV / 4 / 256, 256>>>();

    dim3 go(128, 4);
    gemm_out<<<go, 256, G_SMEM_BYTES>>>(Wo, bo, out);
}

// round 11
// speedup vs baseline: 6.3776x; 1.1430x over previous
#include <cuda_runtime.h>
#include <cuda_fp16.h>
#include <cstdint>
#include <math.h>

#define BB 2
#define LL 8192
#define DIMV 512
#define NH 8
#define HD 64
#define SCALE 0.125f
#define NEG_FILL -100000000.0f
#define ML (BB*LL)

// ---------------- scratch ----------------
__device__ __align__(16) __half g_qh[ML*DIMV];
__device__ __align__(16) __half g_kh[ML*DIMV];
__device__ __align__(16) __half g_vh[ML*DIMV];
__device__ float g_o0[ML*DIMV];
__device__ float g_o1[ML*DIMV];
__device__ float g_o2[ML*DIMV];
__device__ float g_l0[ML*NH];
__device__ float g_l1[ML*NH];
__device__ float g_l2[ML*NH];
__device__ float g_comb[ML*DIMV];

// ---------------- helpers ----------------
__device__ __forceinline__ uint32_t packh2(float lo, float hi) {
    __half2 h = __floats2half2_rn(lo, hi);
    return *reinterpret_cast<uint32_t*>(&h);
}
__device__ __forceinline__ void mma16(float* c, const uint32_t* a, uint32_t b0, uint32_t b1) {
    asm volatile(
        "mma.sync.aligned.m16n8k16.row.col.f32.f16.f16.f32 "
        "{%0,%1,%2,%3}, {%4,%5,%6,%7}, {%8,%9}, {%0,%1,%2,%3};"
        : "+f"(c[0]), "+f"(c[1]), "+f"(c[2]), "+f"(c[3])
        : "r"(a[0]), "r"(a[1]), "r"(a[2]), "r"(a[3]), "r"(b0), "r"(b1));
}
__device__ __forceinline__ void ldsm_x4(uint32_t* r, uint32_t addr) {
    asm volatile("ldmatrix.sync.aligned.m8n8.x4.shared.b16 {%0,%1,%2,%3}, [%4];"
        : "=r"(r[0]), "=r"(r[1]), "=r"(r[2]), "=r"(r[3]) : "r"(addr));
}
__device__ __forceinline__ void ldsm_x4t(uint32_t* r, uint32_t addr) {
    asm volatile("ldmatrix.sync.aligned.m8n8.x4.trans.shared.b16 {%0,%1,%2,%3}, [%4];"
        : "=r"(r[0]), "=r"(r[1]), "=r"(r[2]), "=r"(r[3]) : "r"(addr));
}
__device__ __forceinline__ uint32_t smem_u32(const void* p) {
    uint32_t a;
    asm("{ .reg .u64 t; cvta.to.shared.u64 t, %1; cvt.u32.u64 %0, t; }" : "=r"(a) : "l"(p));
    return a;
}
__device__ __forceinline__ void cp16(uint32_t dst, const void* src) {
    asm volatile("cp.async.cg.shared.global [%0], [%1], 16;" :: "r"(dst), "l"(src));
}
#define CP_COMMIT() asm volatile("cp.async.commit_group;" ::: "memory")
#define CP_WAIT1()  asm volatile("cp.async.wait_group 1;" ::: "memory")
#define CP_WAIT0()  asm volatile("cp.async.wait_group 0;" ::: "memory")

// exp(x*SCALE) with one mul + ex2
__device__ __forceinline__ float expsc(float x) {
    float r;
    asm("ex2.approx.f32 %0, %1;" : "=f"(r) : "f"(x * 0.180336880f));
    return r;
}

// =====================================================================
// fp16-mma GEMM, cp.async double-buffered, 256 thr / 8 warps.
// C[16384,512] = A @ W^T (+bias). CTA 128x128, warp tile 64x32.
// =====================================================================
#define GST 40
#define GBUF (128*GST*2)
#define G_SMEM_BYTES (2*GBUF*4)     // 81920

template <bool OUT_HALF>
__device__ __forceinline__ void gemm_body(const float* __restrict__ A,
                                          const float* __restrict__ W,
                                          const float* __restrict__ bias,
                                          float* __restrict__ Cf,
                                          __half* __restrict__ Ch,
                                          float* smg) {
    uint32_t sb = smem_u32(smg);
    const int t = threadIdx.x, lane = t & 31, w = t >> 5;
    const int g = lane >> 2, tg = lane & 3;
    const int m0 = blockIdx.x * 128, n0 = blockIdx.y * 128;
    const int wm = (w >> 2) * 64, wn = (w & 3) * 32;

    float c[4][4][4];
    #pragma unroll
    for (int i = 0; i < 4; i++)
        #pragma unroll
        for (int j = 0; j < 4; j++)
            #pragma unroll
            for (int q = 0; q < 4; q++) c[i][j][q] = 0.f;

    auto fill = [&](int ck, int buf) {
        #pragma unroll
        for (int r = 0; r < 4; r++) {
            int idx = t + r * 256;
            int row = idx >> 3, c4 = idx & 7;
            uint32_t dstA = sb + (uint32_t)(buf * GBUF + row * GST + c4 * 4) * 4u;
            cp16(dstA, A + (size_t)(m0 + row) * 512 + ck * 32 + c4 * 4);
            uint32_t dstW = sb + (uint32_t)(buf * GBUF + 128 * GST + row * GST + c4 * 4) * 4u;
            cp16(dstW, W + (size_t)(n0 + row) * 512 + ck * 32 + c4 * 4);
        }
        CP_COMMIT();
    };

    fill(0, 0);
    fill(1, 1);

    for (int ck = 0; ck < 16; ck++) {
        if (ck < 15) CP_WAIT1(); else CP_WAIT0();
        __syncthreads();
        const float* As = smg + (ck & 1) * GBUF;
        const float* Ws = As + 128 * GST;
        #pragma unroll
        for (int ks = 0; ks < 2; ks++) {
            uint32_t af[4][4], bf[4][2];
            #pragma unroll
            for (int mt = 0; mt < 4; mt++) {
                int rb = wm + mt * 16;
                float2 x0 = *(const float2*)(As + (rb + g)     * GST + ks*16 + 2*tg);
                float2 x1 = *(const float2*)(As + (rb + g + 8) * GST + ks*16 + 2*tg);
                float2 x2 = *(const float2*)(As + (rb + g)     * GST + ks*16 + 2*tg + 8);
                float2 x3 = *(const float2*)(As + (rb + g + 8) * GST + ks*16 + 2*tg + 8);
                af[mt][0] = packh2(x0.x, x0.y);
                af[mt][1] = packh2(x1.x, x1.y);
                af[mt][2] = packh2(x2.x, x2.y);
                af[mt][3] = packh2(x3.x, x3.y);
            }
            #pragma unroll
            for (int nt = 0; nt < 4; nt++) {
                int rw = wn + nt * 8 + g;
                float2 y0 = *(const float2*)(Ws + rw * GST + ks*16 + 2*tg);
                float2 y1 = *(const float2*)(Ws + rw * GST + ks*16 + 2*tg + 8);
                bf[nt][0] = packh2(y0.x, y0.y);
                bf[nt][1] = packh2(y1.x, y1.y);
            }
            #pragma unroll
            for (int mt = 0; mt < 4; mt++)
                #pragma unroll
                for (int nt = 0; nt < 4; nt++)
                    mma16(c[mt][nt], af[mt], bf[nt][0], bf[nt][1]);
        }
        __syncthreads();
        if (ck + 2 < 16) fill(ck + 2, ck & 1);
    }

    #pragma unroll
    for (int mt = 0; mt < 4; mt++) {
        int row0 = m0 + wm + mt * 16 + g;
        #pragma unroll
        for (int nt = 0; nt < 4; nt++) {
            int col = n0 + wn + nt * 8 + 2 * tg;
            if (OUT_HALF) {
                *(__half2*)(Ch + (size_t)row0 * 512 + col) =
                    __floats2half2_rn(c[mt][nt][0], c[mt][nt][1]);
                *(__half2*)(Ch + (size_t)(row0 + 8) * 512 + col) =
                    __floats2half2_rn(c[mt][nt][2], c[mt][nt][3]);
            } else {
                float b0 = 0.f, b1 = 0.f;
                if (bias) { b0 = bias[col]; b1 = bias[col + 1]; }
                *(float2*)(Cf + (size_t)row0 * 512 + col) =
                    make_float2(c[mt][nt][0] + b0, c[mt][nt][1] + b1);
                *(float2*)(Cf + (size_t)(row0 + 8) * 512 + col) =
                    make_float2(c[mt][nt][2] + b0, c[mt][nt][3] + b1);
            }
        }
    }
}

__global__ __launch_bounds__(256, 2) void gemm_proj(const float* __restrict__ q,
                                                    const float* __restrict__ k,
                                                    const float* __restrict__ v,
                                                    const float* __restrict__ Wq,
                                                    const float* __restrict__ Wk,
                                                    const float* __restrict__ Wv) {
    extern __shared__ float smg[];
    const float* A; const float* W; __half* C;
    if (blockIdx.z == 0)      { A = q; W = Wq; C = g_qh; }
    else if (blockIdx.z == 1) { A = k; W = Wk; C = g_kh; }
    else                      { A = v; W = Wv; C = g_vh; }
    gemm_body<true>(A, W, nullptr, nullptr, C, smg);
}

__global__ __launch_bounds__(256, 2) void gemm_out(const float* __restrict__ Wo,
                                                   const float* __restrict__ bo,
                                                   float* __restrict__ out) {
    extern __shared__ float smg[];
    gemm_body<false>(g_comb, Wo, bo, out, nullptr, smg);
}

// =====================================================================
// fp16-mma flash attention — fully register-resident P, ldmatrix frags.
// CTA = 256 q rows of one (branch,b,seg,h) block -> 896 CTAs, 256 thr.
// Warp: 32 q rows. 16 k-tiles of 64 keys, cp.async double-buffered.
// smem: 2 x (K 64x72 + V 64x72) halves = 36864 B. No P buffer.
// =====================================================================
#define KSTH 72
#define ABUF (64*KSTH)                 // halves per 64-row tile
#define A_SMEM_BYTES (4*ABUF*2)        // 36864

__global__ __launch_bounds__(256, 1) void attn_mma() {
    extern __shared__ __half smh[];
    uint32_t sb = smem_u32(smh);
    const int t = threadIdx.x, lane = t & 31, w = t >> 5;
    const int g = lane >> 2, tg = lane & 3;

    int bid = blockIdx.x;
    int br, rem;
    if (bid < 512)      { br = 0; rem = bid; }
    else if (bid < 768) { br = 1; rem = bid - 512; }
    else                { br = 2; rem = bid - 768; }
    int sl, dr, nseg;
    if (br == 0)      { sl = 1024; dr = 1; nseg = 8; }
    else if (br == 1) { sl = 2048; dr = 2; nseg = 4; }
    else              { sl = 4096; dr = 4; nseg = 2; }
    int qs = rem & 3; rem >>= 2;
    int h  = rem & 7; rem >>= 3;
    int seg = rem % nseg;
    int b   = rem / nseg;
    int off = h / (NH / dr);
    float* og = (br == 0) ? g_o0 : (br == 1) ? g_o1 : g_o2;
    float* lg = (br == 0) ? g_l0 : (br == 1) ? g_l1 : g_l2;
    const size_t baseBL = (size_t)b * LL;

    // ---- stage all 256 Q rows (halves) across the 4 KV regions ----
    #pragma unroll
    for (int i = 0; i < 8; i++) {
        int idx = t + i * 256;
        int row = idx >> 3, c8 = idx & 7;
        int p = seg * sl + (qs * 256 + row) * dr + off;
        cp16(sb + (uint32_t)(row * KSTH + c8 * 8) * 2u,
             g_qh + (baseBL + p) * 512 + h * 64 + c8 * 8);
    }
    CP_COMMIT();
    CP_WAIT0();
    __syncthreads();

    // ---- Q a-frags via ldmatrix.x4 (warp rows w*32 .. w*32+31) ----
    uint32_t qa[2][4][4];
    {
        int rl = w * 32 + (lane & 15);
        int ch = (lane >> 4) * 8;
        #pragma unroll
        for (int mt = 0; mt < 2; mt++)
            #pragma unroll
            for (int ks = 0; ks < 4; ks++)
                ldsm_x4(qa[mt][ks],
                        sb + (uint32_t)((rl + mt*16) * KSTH + ks*16 + ch) * 2u);
    }
    __syncthreads();

    auto fill = [&](int kt, int buf) {
        #pragma unroll
        for (int i = 0; i < 2; i++) {
            int idx = t + i * 256;
            int row = idx >> 3, c8 = idx & 7;
            int p = seg * sl + (kt * 64 + row) * dr + off;
            size_t gidx = (baseBL + p) * 512 + h * 64 + c8 * 8;
            uint32_t dK = sb + (uint32_t)(buf * 2 * ABUF + row * KSTH + c8 * 8) * 2u;
            cp16(dK, g_kh + gidx);
            cp16(dK + ABUF * 2u, g_vh + gidx);
        }
        CP_COMMIT();
    };

    float oc[2][8][4];
    #pragma unroll
    for (int mt = 0; mt < 2; mt++)
        #pragma unroll
        for (int db = 0; db < 8; db++)
            oc[mt][db][0] = oc[mt][db][1] = oc[mt][db][2] = oc[mt][db][3] = 0.f;
    float racc[2][2] = {{0.f, 0.f}, {0.f, 0.f}};

    // per-lane ldmatrix address offsets
    const int kKeyOff = (lane & 7) + ((lane >> 4) & 1) * 8;   // K: bit4 -> +8 keys
    const int kColOff = ((lane >> 3) & 1) * 8;                // K: bit3 -> +8 k
    const int vKeyOff = (lane & 7) + ((lane >> 3) & 1) * 8;   // V: bit3 -> +8 keys
    const int vColOff = ((lane >> 4) & 1) * 8;                // V: bit4 -> +8 d

    fill(0, 0);

    for (int kt = 0; kt < 16; kt++) {
        if (kt < 15) { fill(kt + 1, (kt + 1) & 1); CP_WAIT1(); }
        else CP_WAIT0();
        __syncthreads();
        uint32_t kbase = sb + (uint32_t)((kt & 1) * 2 * ABUF) * 2u;
        uint32_t vbase = kbase + (uint32_t)ABUF * 2u;

        #pragma unroll
        for (int kh = 0; kh < 2; kh++) {
            // ---- S = Q K^T over 32 keys (kb 0..3 of n8) ----
            float sc[2][4][4];
            #pragma unroll
            for (int mt = 0; mt < 2; mt++)
                #pragma unroll
                for (int kb = 0; kb < 4; kb++)
                    sc[mt][kb][0] = sc[mt][kb][1] = sc[mt][kb][2] = sc[mt][kb][3] = 0.f;
            #pragma unroll
            for (int ks = 0; ks < 4; ks++) {
                uint32_t bf[8];
                uint32_t ka = kbase +
                    (uint32_t)((kh*32 + kKeyOff) * KSTH + kColOff + ks*16) * 2u;
                ldsm_x4(bf,     ka);
                ldsm_x4(bf + 4, ka + (uint32_t)(16 * KSTH) * 2u);
                #pragma unroll
                for (int mt = 0; mt < 2; mt++)
                    #pragma unroll
                    for (int kb = 0; kb < 4; kb++)
                        mma16(sc[mt][kb], qa[mt][ks], bf[kb*2], bf[kb*2+1]);
            }

            // ---- P = exp(S*SCALE) packed straight into PV a-frags ----
            uint32_t pf[2][2][4];
            #pragma unroll
            for (int mt = 0; mt < 2; mt++) {
                #pragma unroll
                for (int kbp = 0; kbp < 2; kbp++) {
                    float a0 = expsc(sc[mt][2*kbp][0]),   a1 = expsc(sc[mt][2*kbp][1]);
                    float a2 = expsc(sc[mt][2*kbp][2]),   a3 = expsc(sc[mt][2*kbp][3]);
                    float b0 = expsc(sc[mt][2*kbp+1][0]), b1 = expsc(sc[mt][2*kbp+1][1]);
                    float b2 = expsc(sc[mt][2*kbp+1][2]), b3 = expsc(sc[mt][2*kbp+1][3]);
                    racc[mt][0] += (a0 + a1) + (b0 + b1);
                    racc[mt][1] += (a2 + a3) + (b2 + b3);
                    pf[mt][kbp][0] = packh2(a0, a1);
                    pf[mt][kbp][1] = packh2(a2, a3);
                    pf[mt][kbp][2] = packh2(b0, b1);
                    pf[mt][kbp][3] = packh2(b2, b3);
                }
            }

            // ---- O += P V : V b-frags via ldmatrix.x4.trans ----
            #pragma unroll
            for (int kbp = 0; kbp < 2; kbp++) {
                int key0 = kh*32 + kbp*16;
                #pragma unroll
                for (int dbp = 0; dbp < 4; dbp++) {
                    uint32_t vb[4];
                    ldsm_x4t(vb, vbase +
                        (uint32_t)((key0 + vKeyOff) * KSTH + dbp*16 + vColOff) * 2u);
                    mma16(oc[0][dbp*2],   pf[0][kbp], vb[0], vb[1]);
                    mma16(oc[0][dbp*2+1], pf[0][kbp], vb[2], vb[3]);
                    mma16(oc[1][dbp*2],   pf[1][kbp], vb[0], vb[1]);
                    mma16(oc[1][dbp*2+1], pf[1][kbp], vb[2], vb[3]);
                }
            }
        }
        __syncthreads();
    }

    // ---- reduce row sums across the quad ----
    #pragma unroll
    for (int mt = 0; mt < 2; mt++)
        #pragma unroll
        for (int rs = 0; rs < 2; rs++) {
            float v = racc[mt][rs];
            v += __shfl_xor_sync(0xffffffffu, v, 1);
            v += __shfl_xor_sync(0xffffffffu, v, 2);
            racc[mt][rs] = v;
        }

    // ---- epilogue ----
    #pragma unroll
    for (int mt = 0; mt < 2; mt++) {
        #pragma unroll
        for (int rs = 0; rs < 2; rs++) {
            int qrow = qs * 256 + w * 32 + mt * 16 + g + rs * 8;
            int p = seg * sl + qrow * dr + off;
            float inv = 1.f / racc[mt][rs];
            float* op = og + (baseBL + p) * 512 + h * 64;
            #pragma unroll
            for (int db = 0; db < 8; db++) {
                *(float2*)(op + db * 8 + 2 * tg) =
                    make_float2(oc[mt][db][rs*2+0] * inv, oc[mt][db][rs*2+1] * inv);
            }
            if (tg == 0) {
                float lse = logf(racc[mt][rs]);
                if (lse == 0.0f) lse = NEG_FILL;
                lg[(baseBL + p) * NH + h] = lse;
            }
        }
    }
}

// =====================================================================
// Combine branches with analytic coverage predicates.
// =====================================================================
__global__ __launch_bounds__(256) void combine_kernel() {
    int idx4 = blockIdx.x * blockDim.x + threadIdx.x;
    if (idx4 >= ML * DIMV / 4) return;
    int col4 = idx4 & 127;
    int row  = idx4 >> 7;
    int h    = col4 >> 4;
    int p    = row & (LL - 1);
    int li   = row * NH + h;

    float l1 = g_l0[li];
    float l2 = ((p & 1) == (h >> 2)) ? g_l1[li] : NEG_FILL;
    float l3 = ((p & 3) == (h >> 1)) ? g_l2[li] : NEG_FILL;
    float mm = fmaxf(l1, fmaxf(l2, l3));
    float w1 = __expf(l1 - mm), w2 = __expf(l2 - mm), w3 = __expf(l3 - mm);
    float inv = 1.f / (w1 + w2 + w3);
    w1 *= inv; w2 *= inv; w3 *= inv;

    float4 a = ((const float4*)g_o0)[idx4];
    float4 b = ((const float4*)g_o1)[idx4];
    float4 c = ((const float4*)g_o2)[idx4];
    float4 o;
    o.x = w1*a.x + w2*b.x + w3*c.x;
    o.y = w1*a.y + w2*b.y + w3*c.y;
    o.z = w1*a.z + w2*b.z + w3*c.z;
    o.w = w1*a.w + w2*b.w + w3*c.w;
    ((float4*)g_comb)[idx4] = o;
}

// =====================================================================
extern "C" void kernel_launch(void* const* d_in, const int* in_sizes, int n_in,
                              void* d_out, int out_size) {
    (void)in_sizes; (void)n_in; (void)out_size;
    const float* query = (const float*)d_in[0];
    const float* key_  = (const float*)d_in[1];
    const float* value = (const float*)d_in[2];
    const float* Wq    = (const float*)d_in[3];
    const float* Wk    = (const float*)d_in[4];
    const float* Wv    = (const float*)d_in[5];
    const float* Wo    = (const float*)d_in[6];
    const float* bo    = (const float*)d_in[7];
    float* out = (float*)d_out;

    cudaFuncSetAttribute(gemm_proj, cudaFuncAttributeMaxDynamicSharedMemorySize, G_SMEM_BYTES);
    cudaFuncSetAttribute(gemm_out,  cudaFuncAttributeMaxDynamicSharedMemorySize, G_SMEM_BYTES);
    cudaFuncSetAttribute(attn_mma,  cudaFuncAttributeMaxDynamicSharedMemorySize, A_SMEM_BYTES);

    dim3 gp(128, 4, 3);
    gemm_proj<<<gp, 256, G_SMEM_BYTES>>>(query, key_, value, Wq, Wk, Wv);

    attn_mma<<<896, 256, A_SMEM_BYTES>>>();

    combine_kernel<<<ML * DIMV / 4 / 256, 256>>>();

    dim3 go(128, 4);
    gemm_out<<<go, 256, G_SMEM_BYTES>>>(Wo, bo, out);
}

// round 12
// speedup vs baseline: 6.8257x; 1.0703x over previous
#include <cuda_runtime.h>
#include <cuda_fp16.h>
#include <cstdint>
#include <math.h>

#define BB 2
#define LL 8192
#define DIMV 512
#define NH 8
#define HD 64
#define SCALE 0.125f
#define NEG_FILL -100000000.0f
#define ML (BB*LL)

// ---------------- scratch ----------------
__device__ __align__(16) __half g_qh[ML*DIMV];    // projected Q (half)
__device__ __align__(16) __half g_kh[ML*DIMV];
__device__ __align__(16) __half g_vh[ML*DIMV];
__device__ __align__(16) __half g_xq[ML*DIMV];    // converted inputs (half)
__device__ __align__(16) __half g_xk[ML*DIMV];
__device__ __align__(16) __half g_xv[ML*DIMV];
__device__ __align__(16) __half g_wq[DIMV*DIMV];  // converted weights (half)
__device__ __align__(16) __half g_wk[DIMV*DIMV];
__device__ __align__(16) __half g_wv[DIMV*DIMV];
__device__ __align__(16) __half g_wo[DIMV*DIMV];
__device__ __align__(16) __half g_combh[ML*DIMV]; // combine output (half)
__device__ float g_o0[ML*DIMV];
__device__ float g_o1[ML*DIMV];
__device__ float g_o2[ML*DIMV];
__device__ float g_l0[ML*NH];
__device__ float g_l1[ML*NH];
__device__ float g_l2[ML*NH];

// ---------------- helpers ----------------
__device__ __forceinline__ uint32_t packh2(float lo, float hi) {
    __half2 h = __floats2half2_rn(lo, hi);
    return *reinterpret_cast<uint32_t*>(&h);
}
__device__ __forceinline__ void mma16(float* c, const uint32_t* a, uint32_t b0, uint32_t b1) {
    asm volatile(
        "mma.sync.aligned.m16n8k16.row.col.f32.f16.f16.f32 "
        "{%0,%1,%2,%3}, {%4,%5,%6,%7}, {%8,%9}, {%0,%1,%2,%3};"
        : "+f"(c[0]), "+f"(c[1]), "+f"(c[2]), "+f"(c[3])
        : "r"(a[0]), "r"(a[1]), "r"(a[2]), "r"(a[3]), "r"(b0), "r"(b1));
}
__device__ __forceinline__ void ldsm_x4(uint32_t* r, uint32_t addr) {
    asm volatile("ldmatrix.sync.aligned.m8n8.x4.shared.b16 {%0,%1,%2,%3}, [%4];"
        : "=r"(r[0]), "=r"(r[1]), "=r"(r[2]), "=r"(r[3]) : "r"(addr));
}
__device__ __forceinline__ void ldsm_x4t(uint32_t* r, uint32_t addr) {
    asm volatile("ldmatrix.sync.aligned.m8n8.x4.trans.shared.b16 {%0,%1,%2,%3}, [%4];"
        : "=r"(r[0]), "=r"(r[1]), "=r"(r[2]), "=r"(r[3]) : "r"(addr));
}
__device__ __forceinline__ uint32_t smem_u32(const void* p) {
    uint32_t a;
    asm("{ .reg .u64 t; cvta.to.shared.u64 t, %1; cvt.u32.u64 %0, t; }" : "=r"(a) : "l"(p));
    return a;
}
__device__ __forceinline__ void cp16(uint32_t dst, const void* src) {
    asm volatile("cp.async.cg.shared.global [%0], [%1], 16;" :: "r"(dst), "l"(src));
}
#define CP_COMMIT() asm volatile("cp.async.commit_group;" ::: "memory")
#define CP_WAIT1()  asm volatile("cp.async.wait_group 1;" ::: "memory")
#define CP_WAIT0()  asm volatile("cp.async.wait_group 0;" ::: "memory")

// exp(x*SCALE) with one mul + ex2
__device__ __forceinline__ float expsc(float x) {
    float r;
    asm("ex2.approx.f32 %0, %1;" : "=f"(r) : "f"(x * 0.180336880f));
    return r;
}

// =====================================================================
// fp32 -> fp16 conversion kernels (bandwidth-bound, run once up front)
// =====================================================================
__global__ __launch_bounds__(256) void conv_in(const float* __restrict__ q,
                                               const float* __restrict__ k,
                                               const float* __restrict__ v) {
    const float* src = (blockIdx.y == 0) ? q : (blockIdx.y == 1) ? k : v;
    __half* dst = (blockIdx.y == 0) ? g_xq : (blockIdx.y == 1) ? g_xk : g_xv;
    int i = blockIdx.x * blockDim.x + threadIdx.x;          // over elems/4
    if (i >= ML * DIMV / 4) return;
    float4 a = ((const float4*)src)[i];
    __half2 h0 = __floats2half2_rn(a.x, a.y);
    __half2 h1 = __floats2half2_rn(a.z, a.w);
    ((__half2*)dst)[2*i]   = h0;
    ((__half2*)dst)[2*i+1] = h1;
}
__global__ __launch_bounds__(256) void conv_w(const float* __restrict__ wq,
                                              const float* __restrict__ wk,
                                              const float* __restrict__ wv,
                                              const float* __restrict__ wo) {
    const float* src = (blockIdx.y == 0) ? wq : (blockIdx.y == 1) ? wk :
                       (blockIdx.y == 2) ? wv : wo;
    __half* dst = (blockIdx.y == 0) ? g_wq : (blockIdx.y == 1) ? g_wk :
                  (blockIdx.y == 2) ? g_wv : g_wo;
    int i = blockIdx.x * blockDim.x + threadIdx.x;          // over 512*512/4
    if (i >= DIMV * DIMV / 4) return;
    float4 a = ((const float4*)src)[i];
    ((__half2*)dst)[2*i]   = __floats2half2_rn(a.x, a.y);
    ((__half2*)dst)[2*i+1] = __floats2half2_rn(a.z, a.w);
}

// =====================================================================
// Pure fp16 GEMM: C[16384,512] = A @ W^T (+bias), A/W half in gmem.
// CTA 128x128, 256 thr / 8 warps, warp tile 64x32 (mt4 x nt4).
// BK=64, cp.async 2-stage, ldmatrix fragment loads, stride-72 rows.
// =====================================================================
#define GSTH 72
#define GHBUF (2*128*GSTH)             // halves per stage (A then W)
#define G_SMEM_BYTES (2*GHBUF*2)       // 73728

template <bool OUT_HALF>
__device__ __forceinline__ void gemm_body(const __half* __restrict__ A,
                                          const __half* __restrict__ W,
                                          const float* __restrict__ bias,
                                          float* __restrict__ Cf,
                                          __half* __restrict__ Ch,
                                          __half* smg) {
    uint32_t sb = smem_u32(smg);
    const int t = threadIdx.x, lane = t & 31, w = t >> 5;
    const int g = lane >> 2, tg = lane & 3;
    const int m0 = blockIdx.x * 128, n0 = blockIdx.y * 128;
    const int wm = (w >> 2) * 64, wn = (w & 3) * 32;

    const int aRow = lane & 15,                 aCh = (lane >> 4) * 8;
    const int wRow = (lane & 7) + ((lane >> 4) & 1) * 8, wCh = ((lane >> 3) & 1) * 8;

    float c[4][4][4];
    #pragma unroll
    for (int i = 0; i < 4; i++)
        #pragma unroll
        for (int j = 0; j < 4; j++)
            #pragma unroll
            for (int q = 0; q < 4; q++) c[i][j][q] = 0.f;

    auto fill = [&](int ck, int buf) {
        #pragma unroll
        for (int r = 0; r < 4; r++) {
            int idx = t + r * 256;              // 1024 per matrix
            int row = idx >> 3, c8 = idx & 7;
            uint32_t dA = sb + (uint32_t)(buf * GHBUF + row * GSTH + c8 * 8) * 2u;
            cp16(dA, A + (size_t)(m0 + row) * 512 + ck * 64 + c8 * 8);
            uint32_t dW = sb + (uint32_t)(buf * GHBUF + 128 * GSTH + row * GSTH + c8 * 8) * 2u;
            cp16(dW, W + (size_t)(n0 + row) * 512 + ck * 64 + c8 * 8);
        }
        CP_COMMIT();
    };

    fill(0, 0);
    fill(1, 1);

    for (int ck = 0; ck < 8; ck++) {
        if (ck < 7) CP_WAIT1(); else CP_WAIT0();
        __syncthreads();
        uint32_t abase = sb + (uint32_t)((ck & 1) * GHBUF) * 2u;
        uint32_t wbase = abase + (uint32_t)(128 * GSTH) * 2u;
        #pragma unroll
        for (int ks = 0; ks < 4; ks++) {
            uint32_t af[4][4], bf[8];
            #pragma unroll
            for (int mt = 0; mt < 4; mt++)
                ldsm_x4(af[mt], abase +
                    (uint32_t)((wm + mt*16 + aRow) * GSTH + ks*16 + aCh) * 2u);
            ldsm_x4(bf,     wbase + (uint32_t)((wn + wRow)      * GSTH + ks*16 + wCh) * 2u);
            ldsm_x4(bf + 4, wbase + (uint32_t)((wn + 16 + wRow) * GSTH + ks*16 + wCh) * 2u);
            #pragma unroll
            for (int mt = 0; mt < 4; mt++)
                #pragma unroll
                for (int nt = 0; nt < 4; nt++)
                    mma16(c[mt][nt], af[mt], bf[nt*2], bf[nt*2+1]);
        }
        __syncthreads();
        if (ck + 2 < 8) fill(ck + 2, ck & 1);
    }

    #pragma unroll
    for (int mt = 0; mt < 4; mt++) {
        int row0 = m0 + wm + mt * 16 + g;
        #pragma unroll
        for (int nt = 0; nt < 4; nt++) {
            int col = n0 + wn + nt * 8 + 2 * tg;
            if (OUT_HALF) {
                *(__half2*)(Ch + (size_t)row0 * 512 + col) =
                    __floats2half2_rn(c[mt][nt][0], c[mt][nt][1]);
                *(__half2*)(Ch + (size_t)(row0 + 8) * 512 + col) =
                    __floats2half2_rn(c[mt][nt][2], c[mt][nt][3]);
            } else {
                float b0 = 0.f, b1 = 0.f;
                if (bias) { b0 = bias[col]; b1 = bias[col + 1]; }
                *(float2*)(Cf + (size_t)row0 * 512 + col) =
                    make_float2(c[mt][nt][0] + b0, c[mt][nt][1] + b1);
                *(float2*)(Cf + (size_t)(row0 + 8) * 512 + col) =
                    make_float2(c[mt][nt][2] + b0, c[mt][nt][3] + b1);
            }
        }
    }
}

__global__ __launch_bounds__(256, 2) void gemm_proj() {
    extern __shared__ __half smg[];
    const __half* A; const __half* W; __half* C;
    if (blockIdx.z == 0)      { A = g_xq; W = g_wq; C = g_qh; }
    else if (blockIdx.z == 1) { A = g_xk; W = g_wk; C = g_kh; }
    else                      { A = g_xv; W = g_wv; C = g_vh; }
    gemm_body<true>(A, W, nullptr, nullptr, C, smg);
}

__global__ __launch_bounds__(256, 2) void gemm_out(const float* __restrict__ bo,
                                                   float* __restrict__ out) {
    extern __shared__ __half smg[];
    gemm_body<false>(g_combh, g_wo, bo, out, nullptr, smg);
}

// =====================================================================
// fp16-mma flash attention — register-resident P, ldmatrix frags.
// CTA = 256 q rows of one (branch,b,seg,h) block -> 896 CTAs, 256 thr.
// =====================================================================
#define KSTH 72
#define ABUF (64*KSTH)
#define A_SMEM_BYTES (4*ABUF*2)        // 36864

__global__ __launch_bounds__(256, 1) void attn_mma() {
    extern __shared__ __half smh[];
    uint32_t sb = smem_u32(smh);
    const int t = threadIdx.x, lane = t & 31, w = t >> 5;
    const int g = lane >> 2, tg = lane & 3;

    int bid = blockIdx.x;
    int br, rem;
    if (bid < 512)      { br = 0; rem = bid; }
    else if (bid < 768) { br = 1; rem = bid - 512; }
    else                { br = 2; rem = bid - 768; }
    int sl, dr, nseg;
    if (br == 0)      { sl = 1024; dr = 1; nseg = 8; }
    else if (br == 1) { sl = 2048; dr = 2; nseg = 4; }
    else              { sl = 4096; dr = 4; nseg = 2; }
    int qs = rem & 3; rem >>= 2;
    int h  = rem & 7; rem >>= 3;
    int seg = rem % nseg;
    int b   = rem / nseg;
    int off = h / (NH / dr);
    float* og = (br == 0) ? g_o0 : (br == 1) ? g_o1 : g_o2;
    float* lg = (br == 0) ? g_l0 : (br == 1) ? g_l1 : g_l2;
    const size_t baseBL = (size_t)b * LL;

    // ---- stage all 256 Q rows (halves) across the 4 KV regions ----
    #pragma unroll
    for (int i = 0; i < 8; i++) {
        int idx = t + i * 256;
        int row = idx >> 3, c8 = idx & 7;
        int p = seg * sl + (qs * 256 + row) * dr + off;
        cp16(sb + (uint32_t)(row * KSTH + c8 * 8) * 2u,
             g_qh + (baseBL + p) * 512 + h * 64 + c8 * 8);
    }
    CP_COMMIT();
    CP_WAIT0();
    __syncthreads();

    // ---- Q a-frags via ldmatrix.x4 ----
    uint32_t qa[2][4][4];
    {
        int rl = w * 32 + (lane & 15);
        int ch = (lane >> 4) * 8;
        #pragma unroll
        for (int mt = 0; mt < 2; mt++)
            #pragma unroll
            for (int ks = 0; ks < 4; ks++)
                ldsm_x4(qa[mt][ks],
                        sb + (uint32_t)((rl + mt*16) * KSTH + ks*16 + ch) * 2u);
    }
    __syncthreads();

    auto fill = [&](int kt, int buf) {
        #pragma unroll
        for (int i = 0; i < 2; i++) {
            int idx = t + i * 256;
            int row = idx >> 3, c8 = idx & 7;
            int p = seg * sl + (kt * 64 + row) * dr + off;
            size_t gidx = (baseBL + p) * 512 + h * 64 + c8 * 8;
            uint32_t dK = sb + (uint32_t)(buf * 2 * ABUF + row * KSTH + c8 * 8) * 2u;
            cp16(dK, g_kh + gidx);
            cp16(dK + ABUF * 2u, g_vh + gidx);
        }
        CP_COMMIT();
    };

    float oc[2][8][4];
    #pragma unroll
    for (int mt = 0; mt < 2; mt++)
        #pragma unroll
        for (int db = 0; db < 8; db++)
            oc[mt][db][0] = oc[mt][db][1] = oc[mt][db][2] = oc[mt][db][3] = 0.f;
    float racc[2][2] = {{0.f, 0.f}, {0.f, 0.f}};

    const int kKeyOff = (lane & 7) + ((lane >> 4) & 1) * 8;
    const int kColOff = ((lane >> 3) & 1) * 8;
    const int vKeyOff = (lane & 7) + ((lane >> 3) & 1) * 8;
    const int vColOff = ((lane >> 4) & 1) * 8;

    fill(0, 0);

    for (int kt = 0; kt < 16; kt++) {
        if (kt < 15) { fill(kt + 1, (kt + 1) & 1); CP_WAIT1(); }
        else CP_WAIT0();
        __syncthreads();
        uint32_t kbase = sb + (uint32_t)((kt & 1) * 2 * ABUF) * 2u;
        uint32_t vbase = kbase + (uint32_t)ABUF * 2u;

        #pragma unroll
        for (int kh = 0; kh < 2; kh++) {
            float sc[2][4][4];
            #pragma unroll
            for (int mt = 0; mt < 2; mt++)
                #pragma unroll
                for (int kb = 0; kb < 4; kb++)
                    sc[mt][kb][0] = sc[mt][kb][1] = sc[mt][kb][2] = sc[mt][kb][3] = 0.f;
            #pragma unroll
            for (int ks = 0; ks < 4; ks++) {
                uint32_t bf[8];
                uint32_t ka = kbase +
                    (uint32_t)((kh*32 + kKeyOff) * KSTH + kColOff + ks*16) * 2u;
                ldsm_x4(bf,     ka);
                ldsm_x4(bf + 4, ka + (uint32_t)(16 * KSTH) * 2u);
                #pragma unroll
                for (int mt = 0; mt < 2; mt++)
                    #pragma unroll
                    for (int kb = 0; kb < 4; kb++)
                        mma16(sc[mt][kb], qa[mt][ks], bf[kb*2], bf[kb*2+1]);
            }

            uint32_t pf[2][2][4];
            #pragma unroll
            for (int mt = 0; mt < 2; mt++) {
                #pragma unroll
                for (int kbp = 0; kbp < 2; kbp++) {
                    float a0 = expsc(sc[mt][2*kbp][0]),   a1 = expsc(sc[mt][2*kbp][1]);
                    float a2 = expsc(sc[mt][2*kbp][2]),   a3 = expsc(sc[mt][2*kbp][3]);
                    float b0 = expsc(sc[mt][2*kbp+1][0]), b1 = expsc(sc[mt][2*kbp+1][1]);
                    float b2 = expsc(sc[mt][2*kbp+1][2]), b3 = expsc(sc[mt][2*kbp+1][3]);
                    racc[mt][0] += (a0 + a1) + (b0 + b1);
                    racc[mt][1] += (a2 + a3) + (b2 + b3);
                    pf[mt][kbp][0] = packh2(a0, a1);
                    pf[mt][kbp][1] = packh2(a2, a3);
                    pf[mt][kbp][2] = packh2(b0, b1);
                    pf[mt][kbp][3] = packh2(b2, b3);
                }
            }

            #pragma unroll
            for (int kbp = 0; kbp < 2; kbp++) {
                int key0 = kh*32 + kbp*16;
                #pragma unroll
                for (int dbp = 0; dbp < 4; dbp++) {
                    uint32_t vb[4];
                    ldsm_x4t(vb, vbase +
                        (uint32_t)((key0 + vKeyOff) * KSTH + dbp*16 + vColOff) * 2u);
                    mma16(oc[0][dbp*2],   pf[0][kbp], vb[0], vb[1]);
                    mma16(oc[0][dbp*2+1], pf[0][kbp], vb[2], vb[3]);
                    mma16(oc[1][dbp*2],   pf[1][kbp], vb[0], vb[1]);
                    mma16(oc[1][dbp*2+1], pf[1][kbp], vb[2], vb[3]);
                }
            }
        }
        __syncthreads();
    }

    #pragma unroll
    for (int mt = 0; mt < 2; mt++)
        #pragma unroll
        for (int rs = 0; rs < 2; rs++) {
            float v = racc[mt][rs];
            v += __shfl_xor_sync(0xffffffffu, v, 1);
            v += __shfl_xor_sync(0xffffffffu, v, 2);
            racc[mt][rs] = v;
        }

    #pragma unroll
    for (int mt = 0; mt < 2; mt++) {
        #pragma unroll
        for (int rs = 0; rs < 2; rs++) {
            int qrow = qs * 256 + w * 32 + mt * 16 + g + rs * 8;
            int p = seg * sl + qrow * dr + off;
            float inv = 1.f / racc[mt][rs];
            float* op = og + (baseBL + p) * 512 + h * 64;
            #pragma unroll
            for (int db = 0; db < 8; db++) {
                *(float2*)(op + db * 8 + 2 * tg) =
                    make_float2(oc[mt][db][rs*2+0] * inv, oc[mt][db][rs*2+1] * inv);
            }
            if (tg == 0) {
                float lse = logf(racc[mt][rs]);
                if (lse == 0.0f) lse = NEG_FILL;
                lg[(baseBL + p) * NH + h] = lse;
            }
        }
    }
}

// =====================================================================
// Combine branches (writes half for the output GEMM).
// =====================================================================
__global__ __launch_bounds__(256) void combine_kernel() {
    int idx4 = blockIdx.x * blockDim.x + threadIdx.x;
    if (idx4 >= ML * DIMV / 4) return;
    int col4 = idx4 & 127;
    int row  = idx4 >> 7;
    int h    = col4 >> 4;
    int p    = row & (LL - 1);
    int li   = row * NH + h;

    float l1 = g_l0[li];
    float l2 = ((p & 1) == (h >> 2)) ? g_l1[li] : NEG_FILL;
    float l3 = ((p & 3) == (h >> 1)) ? g_l2[li] : NEG_FILL;
    float mm = fmaxf(l1, fmaxf(l2, l3));
    float w1 = __expf(l1 - mm), w2 = __expf(l2 - mm), w3 = __expf(l3 - mm);
    float inv = 1.f / (w1 + w2 + w3);
    w1 *= inv; w2 *= inv; w3 *= inv;

    float4 a = ((const float4*)g_o0)[idx4];
    float4 b = ((const float4*)g_o1)[idx4];
    float4 c = ((const float4*)g_o2)[idx4];
    float ox = w1*a.x + w2*b.x + w3*c.x;
    float oy = w1*a.y + w2*b.y + w3*c.y;
    float oz = w1*a.z + w2*b.z + w3*c.z;
    float ow = w1*a.w + w2*b.w + w3*c.w;
    ((__half2*)g_combh)[2*idx4]   = __floats2half2_rn(ox, oy);
    ((__half2*)g_combh)[2*idx4+1] = __floats2half2_rn(oz, ow);
}

// =====================================================================
extern "C" void kernel_launch(void* const* d_in, const int* in_sizes, int n_in,
                              void* d_out, int out_size) {
    (void)in_sizes; (void)n_in; (void)out_size;
    const float* query = (const float*)d_in[0];
    const float* key_  = (const float*)d_in[1];
    const float* value = (const float*)d_in[2];
    const float* Wq    = (const float*)d_in[3];
    const float* Wk    = (const float*)d_in[4];
    const float* Wv    = (const float*)d_in[5];
    const float* Wo    = (const float*)d_in[6];
    const float* bo    = (const float*)d_in[7];
    float* out = (float*)d_out;

    cudaFuncSetAttribute(gemm_proj, cudaFuncAttributeMaxDynamicSharedMemorySize, G_SMEM_BYTES);
    cudaFuncSetAttribute(gemm_out,  cudaFuncAttributeMaxDynamicSharedMemorySize, G_SMEM_BYTES);
    cudaFuncSetAttribute(attn_mma,  cudaFuncAttributeMaxDynamicSharedMemorySize, A_SMEM_BYTES);

    {
        dim3 gi((ML * DIMV / 4 + 255) / 256, 3);
        conv_in<<<gi, 256>>>(query, key_, value);
        dim3 gw((DIMV * DIMV / 4 + 255) / 256, 4);
        conv_w<<<gw, 256>>>(Wq, Wk, Wv, Wo);
    }

    dim3 gp(128, 4, 3);
    gemm_proj<<<gp, 256, G_SMEM_BYTES>>>();

    attn_mma<<<896, 256, A_SMEM_BYTES>>>();

    combine_kernel<<<ML * DIMV / 4 / 256, 256>>>();

    dim3 go(128, 4);
    gemm_out<<<go, 256, G_SMEM_BYTES>>>(bo, out);
}

// round 13
// speedup vs baseline: 7.0006x; 1.0256x over previous
#include <cuda_runtime.h>
#include <cuda_fp16.h>
#include <cstdint>
#include <math.h>

#define BB 2
#define LL 8192
#define DIMV 512
#define NH 8
#define HD 64
#define NEG_FILL -100000000.0f
#define ML (BB*LL)
#define QPRESCALE 0.180336880f   // SCALE * log2(e)
#define ONESH2 0x3C003C00u       // half2(1.0, 1.0)

// ---------------- scratch ----------------
__device__ __align__(16) __half g_qh[ML*DIMV];    // projected Q (half, pre-scaled by SCALE*log2e)
__device__ __align__(16) __half g_kh[ML*DIMV];
__device__ __align__(16) __half g_vh[ML*DIMV];
__device__ __align__(16) __half g_xq[ML*DIMV];
__device__ __align__(16) __half g_xk[ML*DIMV];
__device__ __align__(16) __half g_xv[ML*DIMV];
__device__ __align__(16) __half g_wq[DIMV*DIMV];
__device__ __align__(16) __half g_wk[DIMV*DIMV];
__device__ __align__(16) __half g_wv[DIMV*DIMV];
__device__ __align__(16) __half g_wo[DIMV*DIMV];
__device__ __align__(16) __half g_combh[ML*DIMV];
__device__ __align__(16) __half g_o0[ML*DIMV];    // branch outputs in half
__device__ __align__(16) __half g_o1[ML*DIMV];
__device__ __align__(16) __half g_o2[ML*DIMV];
__device__ float g_l0[ML*NH];
__device__ float g_l1[ML*NH];
__device__ float g_l2[ML*NH];

// ---------------- helpers ----------------
__device__ __forceinline__ uint32_t packh2(float lo, float hi) {
    __half2 h = __floats2half2_rn(lo, hi);
    return *reinterpret_cast<uint32_t*>(&h);
}
__device__ __forceinline__ void mma16(float* c, const uint32_t* a, uint32_t b0, uint32_t b1) {
    asm volatile(
        "mma.sync.aligned.m16n8k16.row.col.f32.f16.f16.f32 "
        "{%0,%1,%2,%3}, {%4,%5,%6,%7}, {%8,%9}, {%0,%1,%2,%3};"
        : "+f"(c[0]), "+f"(c[1]), "+f"(c[2]), "+f"(c[3])
        : "r"(a[0]), "r"(a[1]), "r"(a[2]), "r"(a[3]), "r"(b0), "r"(b1));
}
__device__ __forceinline__ void ldsm_x4(uint32_t* r, uint32_t addr) {
    asm volatile("ldmatrix.sync.aligned.m8n8.x4.shared.b16 {%0,%1,%2,%3}, [%4];"
        : "=r"(r[0]), "=r"(r[1]), "=r"(r[2]), "=r"(r[3]) : "r"(addr));
}
__device__ __forceinline__ void ldsm_x4t(uint32_t* r, uint32_t addr) {
    asm volatile("ldmatrix.sync.aligned.m8n8.x4.trans.shared.b16 {%0,%1,%2,%3}, [%4];"
        : "=r"(r[0]), "=r"(r[1]), "=r"(r[2]), "=r"(r[3]) : "r"(addr));
}
__device__ __forceinline__ uint32_t smem_u32(const void* p) {
    uint32_t a;
    asm("{ .reg .u64 t; cvta.to.shared.u64 t, %1; cvt.u32.u64 %0, t; }" : "=r"(a) : "l"(p));
    return a;
}
__device__ __forceinline__ void cp16(uint32_t dst, const void* src) {
    asm volatile("cp.async.cg.shared.global [%0], [%1], 16;" :: "r"(dst), "l"(src));
}
#define CP_COMMIT() asm volatile("cp.async.commit_group;" ::: "memory")
#define CP_WAIT1()  asm volatile("cp.async.wait_group 1;" ::: "memory")
#define CP_WAIT0()  asm volatile("cp.async.wait_group 0;" ::: "memory")

// P = 2^S (S already includes SCALE*log2e via the Q projection)
__device__ __forceinline__ float ex2f(float x) {
    float r;
    asm("ex2.approx.f32 %0, %1;" : "=f"(r) : "f"(x));
    return r;
}

// =====================================================================
// fp32 -> fp16 conversion kernels
// =====================================================================
__global__ __launch_bounds__(256) void conv_in(const float* __restrict__ q,
                                               const float* __restrict__ k,
                                               const float* __restrict__ v) {
    const float* src = (blockIdx.y == 0) ? q : (blockIdx.y == 1) ? k : v;
    __half* dst = (blockIdx.y == 0) ? g_xq : (blockIdx.y == 1) ? g_xk : g_xv;
    int i = blockIdx.x * blockDim.x + threadIdx.x;
    if (i >= ML * DIMV / 4) return;
    float4 a = ((const float4*)src)[i];
    ((__half2*)dst)[2*i]   = __floats2half2_rn(a.x, a.y);
    ((__half2*)dst)[2*i+1] = __floats2half2_rn(a.z, a.w);
}
__global__ __launch_bounds__(256) void conv_w(const float* __restrict__ wq,
                                              const float* __restrict__ wk,
                                              const float* __restrict__ wv,
                                              const float* __restrict__ wo) {
    const float* src = (blockIdx.y == 0) ? wq : (blockIdx.y == 1) ? wk :
                       (blockIdx.y == 2) ? wv : wo;
    __half* dst = (blockIdx.y == 0) ? g_wq : (blockIdx.y == 1) ? g_wk :
                  (blockIdx.y == 2) ? g_wv : g_wo;
    int i = blockIdx.x * blockDim.x + threadIdx.x;
    if (i >= DIMV * DIMV / 4) return;
    float4 a = ((const float4*)src)[i];
    ((__half2*)dst)[2*i]   = __floats2half2_rn(a.x, a.y);
    ((__half2*)dst)[2*i+1] = __floats2half2_rn(a.z, a.w);
}

// =====================================================================
// Pure fp16 GEMM: C[16384,512] = A @ W^T (+bias).
// CTA 128x128, 256 thr / 8 warps, warp tile 64x32, BK=64, ldmatrix.
// =====================================================================
#define GSTH 72
#define GHBUF (2*128*GSTH)
#define G_SMEM_BYTES (2*GHBUF*2)       // 73728

template <bool OUT_HALF>
__device__ __forceinline__ void gemm_body(const __half* __restrict__ A,
                                          const __half* __restrict__ W,
                                          const float* __restrict__ bias,
                                          float* __restrict__ Cf,
                                          __half* __restrict__ Ch,
                                          float oscale,
                                          __half* smg) {
    uint32_t sb = smem_u32(smg);
    const int t = threadIdx.x, lane = t & 31, w = t >> 5;
    const int g = lane >> 2, tg = lane & 3;
    const int m0 = blockIdx.x * 128, n0 = blockIdx.y * 128;
    const int wm = (w >> 2) * 64, wn = (w & 3) * 32;

    const int aRow = lane & 15,                 aCh = (lane >> 4) * 8;
    const int wRow = (lane & 7) + ((lane >> 4) & 1) * 8, wCh = ((lane >> 3) & 1) * 8;

    float c[4][4][4];
    #pragma unroll
    for (int i = 0; i < 4; i++)
        #pragma unroll
        for (int j = 0; j < 4; j++)
            #pragma unroll
            for (int q = 0; q < 4; q++) c[i][j][q] = 0.f;

    auto fill = [&](int ck, int buf) {
        #pragma unroll
        for (int r = 0; r < 4; r++) {
            int idx = t + r * 256;
            int row = idx >> 3, c8 = idx & 7;
            uint32_t dA = sb + (uint32_t)(buf * GHBUF + row * GSTH + c8 * 8) * 2u;
            cp16(dA, A + (size_t)(m0 + row) * 512 + ck * 64 + c8 * 8);
            uint32_t dW = sb + (uint32_t)(buf * GHBUF + 128 * GSTH + row * GSTH + c8 * 8) * 2u;
            cp16(dW, W + (size_t)(n0 + row) * 512 + ck * 64 + c8 * 8);
        }
        CP_COMMIT();
    };

    fill(0, 0);
    fill(1, 1);

    for (int ck = 0; ck < 8; ck++) {
        if (ck < 7) CP_WAIT1(); else CP_WAIT0();
        __syncthreads();
        uint32_t abase = sb + (uint32_t)((ck & 1) * GHBUF) * 2u;
        uint32_t wbase = abase + (uint32_t)(128 * GSTH) * 2u;
        #pragma unroll
        for (int ks = 0; ks < 4; ks++) {
            uint32_t af[4][4], bf[8];
            #pragma unroll
            for (int mt = 0; mt < 4; mt++)
                ldsm_x4(af[mt], abase +
                    (uint32_t)((wm + mt*16 + aRow) * GSTH + ks*16 + aCh) * 2u);
            ldsm_x4(bf,     wbase + (uint32_t)((wn + wRow)      * GSTH + ks*16 + wCh) * 2u);
            ldsm_x4(bf + 4, wbase + (uint32_t)((wn + 16 + wRow) * GSTH + ks*16 + wCh) * 2u);
            #pragma unroll
            for (int mt = 0; mt < 4; mt++)
                #pragma unroll
                for (int nt = 0; nt < 4; nt++)
                    mma16(c[mt][nt], af[mt], bf[nt*2], bf[nt*2+1]);
        }
        __syncthreads();
        if (ck + 2 < 8) fill(ck + 2, ck & 1);
    }

    #pragma unroll
    for (int mt = 0; mt < 4; mt++) {
        int row0 = m0 + wm + mt * 16 + g;
        #pragma unroll
        for (int nt = 0; nt < 4; nt++) {
            int col = n0 + wn + nt * 8 + 2 * tg;
            if (OUT_HALF) {
                *(__half2*)(Ch + (size_t)row0 * 512 + col) =
                    __floats2half2_rn(c[mt][nt][0] * oscale, c[mt][nt][1] * oscale);
                *(__half2*)(Ch + (size_t)(row0 + 8) * 512 + col) =
                    __floats2half2_rn(c[mt][nt][2] * oscale, c[mt][nt][3] * oscale);
            } else {
                float b0 = 0.f, b1 = 0.f;
                if (bias) { b0 = bias[col]; b1 = bias[col + 1]; }
                *(float2*)(Cf + (size_t)row0 * 512 + col) =
                    make_float2(c[mt][nt][0] + b0, c[mt][nt][1] + b1);
                *(float2*)(Cf + (size_t)(row0 + 8) * 512 + col) =
                    make_float2(c[mt][nt][2] + b0, c[mt][nt][3] + b1);
            }
        }
    }
}

__global__ __launch_bounds__(256, 2) void gemm_proj() {
    extern __shared__ __half smg[];
    const __half* A; const __half* W; __half* C; float sc;
    if (blockIdx.z == 0)      { A = g_xq; W = g_wq; C = g_qh; sc = QPRESCALE; }
    else if (blockIdx.z == 1) { A = g_xk; W = g_wk; C = g_kh; sc = 1.0f; }
    else                      { A = g_xv; W = g_wv; C = g_vh; sc = 1.0f; }
    gemm_body<true>(A, W, nullptr, nullptr, C, sc, smg);
}

__global__ __launch_bounds__(256, 2) void gemm_out(const float* __restrict__ bo,
                                                   float* __restrict__ out) {
    extern __shared__ __half smg[];
    gemm_body<false>(g_combh, g_wo, bo, out, nullptr, 1.0f, smg);
}

// =====================================================================
// fp16-mma flash attention — register P, ldmatrix frags, ones-mma sums.
// CTA = 256 q rows of one (branch,b,seg,h) block -> 896 CTAs, 256 thr.
// =====================================================================
#define KSTH 72
#define ABUF (64*KSTH)
#define A_SMEM_BYTES (4*ABUF*2)        // 36864

__global__ __launch_bounds__(256, 1) void attn_mma() {
    extern __shared__ __half smh[];
    uint32_t sb = smem_u32(smh);
    const int t = threadIdx.x, lane = t & 31, w = t >> 5;
    const int g = lane >> 2, tg = lane & 3;

    int bid = blockIdx.x;
    int br, rem;
    if (bid < 512)      { br = 0; rem = bid; }
    else if (bid < 768) { br = 1; rem = bid - 512; }
    else                { br = 2; rem = bid - 768; }
    int sl, dr, nseg;
    if (br == 0)      { sl = 1024; dr = 1; nseg = 8; }
    else if (br == 1) { sl = 2048; dr = 2; nseg = 4; }
    else              { sl = 4096; dr = 4; nseg = 2; }
    int qs = rem & 3; rem >>= 2;
    int h  = rem & 7; rem >>= 3;
    int seg = rem % nseg;
    int b   = rem / nseg;
    int off = h / (NH / dr);
    __half* og = (br == 0) ? g_o0 : (br == 1) ? g_o1 : g_o2;
    float*  lg = (br == 0) ? g_l0 : (br == 1) ? g_l1 : g_l2;
    const size_t baseBL = (size_t)b * LL;

    // ---- stage all 256 Q rows across the 4 KV regions ----
    #pragma unroll
    for (int i = 0; i < 8; i++) {
        int idx = t + i * 256;
        int row = idx >> 3, c8 = idx & 7;
        int p = seg * sl + (qs * 256 + row) * dr + off;
        cp16(sb + (uint32_t)(row * KSTH + c8 * 8) * 2u,
             g_qh + (baseBL + p) * 512 + h * 64 + c8 * 8);
    }
    CP_COMMIT();
    CP_WAIT0();
    __syncthreads();

    // ---- Q a-frags via ldmatrix.x4 ----
    uint32_t qa[2][4][4];
    {
        int rl = w * 32 + (lane & 15);
        int ch = (lane >> 4) * 8;
        #pragma unroll
        for (int mt = 0; mt < 2; mt++)
            #pragma unroll
            for (int ks = 0; ks < 4; ks++)
                ldsm_x4(qa[mt][ks],
                        sb + (uint32_t)((rl + mt*16) * KSTH + ks*16 + ch) * 2u);
    }
    __syncthreads();

    auto fill = [&](int kt, int buf) {
        #pragma unroll
        for (int i = 0; i < 2; i++) {
            int idx = t + i * 256;
            int row = idx >> 3, c8 = idx & 7;
            int p = seg * sl + (kt * 64 + row) * dr + off;
            size_t gidx = (baseBL + p) * 512 + h * 64 + c8 * 8;
            uint32_t dK = sb + (uint32_t)(buf * 2 * ABUF + row * KSTH + c8 * 8) * 2u;
            cp16(dK, g_kh + gidx);
            cp16(dK + ABUF * 2u, g_vh + gidx);
        }
        CP_COMMIT();
    };

    float oc[2][8][4];
    #pragma unroll
    for (int mt = 0; mt < 2; mt++)
        #pragma unroll
        for (int db = 0; db < 8; db++)
            oc[mt][db][0] = oc[mt][db][1] = oc[mt][db][2] = oc[mt][db][3] = 0.f;
    float rsum[2][4];   // ones-mma accumulator: [0]=row g, [2]=row g+8
    #pragma unroll
    for (int mt = 0; mt < 2; mt++)
        rsum[mt][0] = rsum[mt][1] = rsum[mt][2] = rsum[mt][3] = 0.f;

    const int kKeyOff = (lane & 7) + ((lane >> 4) & 1) * 8;
    const int kColOff = ((lane >> 3) & 1) * 8;
    const int vKeyOff = (lane & 7) + ((lane >> 3) & 1) * 8;
    const int vColOff = ((lane >> 4) & 1) * 8;

    fill(0, 0);

    for (int kt = 0; kt < 16; kt++) {
        if (kt < 15) { fill(kt + 1, (kt + 1) & 1); CP_WAIT1(); }
        else CP_WAIT0();
        __syncthreads();
        uint32_t kbase = sb + (uint32_t)((kt & 1) * 2 * ABUF) * 2u;
        uint32_t vbase = kbase + (uint32_t)ABUF * 2u;

        #pragma unroll
        for (int kh = 0; kh < 2; kh++) {
            // ---- S = Q K^T over 32 keys (already in log2 domain) ----
            float sc[2][4][4];
            #pragma unroll
            for (int mt = 0; mt < 2; mt++)
                #pragma unroll
                for (int kb = 0; kb < 4; kb++)
                    sc[mt][kb][0] = sc[mt][kb][1] = sc[mt][kb][2] = sc[mt][kb][3] = 0.f;
            #pragma unroll
            for (int ks = 0; ks < 4; ks++) {
                uint32_t bf[8];
                uint32_t ka = kbase +
                    (uint32_t)((kh*32 + kKeyOff) * KSTH + kColOff + ks*16) * 2u;
                ldsm_x4(bf,     ka);
                ldsm_x4(bf + 4, ka + (uint32_t)(16 * KSTH) * 2u);
                #pragma unroll
                for (int mt = 0; mt < 2; mt++)
                    #pragma unroll
                    for (int kb = 0; kb < 4; kb++)
                        mma16(sc[mt][kb], qa[mt][ks], bf[kb*2], bf[kb*2+1]);
            }

            // ---- P = 2^S packed straight into PV a-frags; sums via ones-mma ----
            uint32_t pf[2][2][4];
            #pragma unroll
            for (int mt = 0; mt < 2; mt++) {
                #pragma unroll
                for (int kbp = 0; kbp < 2; kbp++) {
                    float a0 = ex2f(sc[mt][2*kbp][0]),   a1 = ex2f(sc[mt][2*kbp][1]);
                    float a2 = ex2f(sc[mt][2*kbp][2]),   a3 = ex2f(sc[mt][2*kbp][3]);
                    float b0 = ex2f(sc[mt][2*kbp+1][0]), b1 = ex2f(sc[mt][2*kbp+1][1]);
                    float b2 = ex2f(sc[mt][2*kbp+1][2]), b3 = ex2f(sc[mt][2*kbp+1][3]);
                    pf[mt][kbp][0] = packh2(a0, a1);
                    pf[mt][kbp][1] = packh2(a2, a3);
                    pf[mt][kbp][2] = packh2(b0, b1);
                    pf[mt][kbp][3] = packh2(b2, b3);
                    mma16(rsum[mt], pf[mt][kbp], ONESH2, ONESH2);
                }
            }

            // ---- O += P V ----
            #pragma unroll
            for (int kbp = 0; kbp < 2; kbp++) {
                int key0 = kh*32 + kbp*16;
                #pragma unroll
                for (int dbp = 0; dbp < 4; dbp++) {
                    uint32_t vb[4];
                    ldsm_x4t(vb, vbase +
                        (uint32_t)((key0 + vKeyOff) * KSTH + dbp*16 + vColOff) * 2u);
                    mma16(oc[0][dbp*2],   pf[0][kbp], vb[0], vb[1]);
                    mma16(oc[0][dbp*2+1], pf[0][kbp], vb[2], vb[3]);
                    mma16(oc[1][dbp*2],   pf[1][kbp], vb[0], vb[1]);
                    mma16(oc[1][dbp*2+1], pf[1][kbp], vb[2], vb[3]);
                }
            }
        }
        __syncthreads();
    }

    // ---- epilogue (row sums already complete per lane via ones-mma) ----
    #pragma unroll
    for (int mt = 0; mt < 2; mt++) {
        #pragma unroll
        for (int rs = 0; rs < 2; rs++) {
            float rsv = rsum[mt][rs*2];
            int qrow = qs * 256 + w * 32 + mt * 16 + g + rs * 8;
            int p = seg * sl + qrow * dr + off;
            float inv = 1.f / rsv;
            __half* op = og + (baseBL + p) * 512 + h * 64;
            #pragma unroll
            for (int db = 0; db < 8; db++) {
                *(__half2*)(op + db * 8 + 2 * tg) =
                    __floats2half2_rn(oc[mt][db][rs*2+0] * inv,
                                      oc[mt][db][rs*2+1] * inv);
            }
            if (tg == 0) {
                float lse = logf(rsv);
                if (lse == 0.0f) lse = NEG_FILL;
                lg[(baseBL + p) * NH + h] = lse;
            }
        }
    }
}

// =====================================================================
// Combine branches (half inputs, half output).
// =====================================================================
__global__ __launch_bounds__(256) void combine_kernel() {
    int idx4 = blockIdx.x * blockDim.x + threadIdx.x;   // 4 elements each
    if (idx4 >= ML * DIMV / 4) return;
    int col4 = idx4 & 127;
    int row  = idx4 >> 7;
    int h    = col4 >> 4;
    int p    = row & (LL - 1);
    int li   = row * NH + h;

    float l1 = g_l0[li];
    float l2 = ((p & 1) == (h >> 2)) ? g_l1[li] : NEG_FILL;
    float l3 = ((p & 3) == (h >> 1)) ? g_l2[li] : NEG_FILL;
    float mm = fmaxf(l1, fmaxf(l2, l3));
    float w1 = __expf(l1 - mm), w2 = __expf(l2 - mm), w3 = __expf(l3 - mm);
    float inv = 1.f / (w1 + w2 + w3);
    w1 *= inv; w2 *= inv; w3 *= inv;

    __half2 a0 = ((const __half2*)g_o0)[2*idx4], a1 = ((const __half2*)g_o0)[2*idx4+1];
    __half2 b0 = ((const __half2*)g_o1)[2*idx4], b1 = ((const __half2*)g_o1)[2*idx4+1];
    __half2 c0 = ((const __half2*)g_o2)[2*idx4], c1 = ((const __half2*)g_o2)[2*idx4+1];
    float2 af0 = __half22float2(a0), af1 = __half22float2(a1);
    float2 bf0 = __half22float2(b0), bf1 = __half22float2(b1);
    float2 cf0 = __half22float2(c0), cf1 = __half22float2(c1);

    float ox = w1*af0.x + w2*bf0.x + w3*cf0.x;
    float oy = w1*af0.y + w2*bf0.y + w3*cf0.y;
    float oz = w1*af1.x + w2*bf1.x + w3*cf1.x;
    float ow = w1*af1.y + w2*bf1.y + w3*cf1.y;
    ((__half2*)g_combh)[2*idx4]   = __floats2half2_rn(ox, oy);
    ((__half2*)g_combh)[2*idx4+1] = __floats2half2_rn(oz, ow);
}

// =====================================================================
extern "C" void kernel_launch(void* const* d_in, const int* in_sizes, int n_in,
                              void* d_out, int out_size) {
    (void)in_sizes; (void)n_in; (void)out_size;
    const float* query = (const float*)d_in[0];
    const float* key_  = (const float*)d_in[1];
    const float* value = (const float*)d_in[2];
    const float* Wq    = (const float*)d_in[3];
    const float* Wk    = (const float*)d_in[4];
    const float* Wv    = (const float*)d_in[5];
    const float* Wo    = (const float*)d_in[6];
    const float* bo    = (const float*)d_in[7];
    float* out = (float*)d_out;

    cudaFuncSetAttribute(gemm_proj, cudaFuncAttributeMaxDynamicSharedMemorySize, G_SMEM_BYTES);
    cudaFuncSetAttribute(gemm_out,  cudaFuncAttributeMaxDynamicSharedMemorySize, G_SMEM_BYTES);
    cudaFuncSetAttribute(attn_mma,  cudaFuncAttributeMaxDynamicSharedMemorySize, A_SMEM_BYTES);

    {
        dim3 gi((ML * DIMV / 4 + 255) / 256, 3);
        conv_in<<<gi, 256>>>(query, key_, value);
        dim3 gw((DIMV * DIMV / 4 + 255) / 256, 4);
        conv_w<<<gw, 256>>>(Wq, Wk, Wv, Wo);
    }

    dim3 gp(128, 4, 3);
    gemm_proj<<<gp, 256, G_SMEM_BYTES>>>();

    attn_mma<<<896, 256, A_SMEM_BYTES>>>();

    combine_kernel<<<ML * DIMV / 4 / 256, 256>>>();

    dim3 go(128, 4);
    gemm_out<<<go, 256, G_SMEM_BYTES>>>(bo, out);
}

// round 14
// speedup vs baseline: 7.1388x; 1.0197x over previous
#include <cuda_runtime.h>
#include <cuda_fp16.h>
#include <cstdint>
#include <math.h>

#define BB 2
#define LL 8192
#define DIMV 512
#define NH 8
#define HD 64
#define NEG_FILL -100000000.0f
#define ML (BB*LL)
#define QPRESCALE 0.180336880f   // SCALE * log2(e)
#define ONESH2 0x3C003C00u       // half2(1.0, 1.0)

// ---------------- scratch ----------------
__device__ __align__(16) __half g_qh[ML*DIMV];    // projected Q (half, pre-scaled by SCALE*log2e)
__device__ __align__(16) __half g_kh[ML*DIMV];
__device__ __align__(16) __half g_vh[ML*DIMV];
__device__ __align__(16) __half g_xq[ML*DIMV];
__device__ __align__(16) __half g_xk[ML*DIMV];
__device__ __align__(16) __half g_xv[ML*DIMV];
__device__ __align__(16) __half g_wq[DIMV*DIMV];
__device__ __align__(16) __half g_wk[DIMV*DIMV];
__device__ __align__(16) __half g_wv[DIMV*DIMV];
__device__ __align__(16) __half g_wo[DIMV*DIMV];
__device__ __align__(16) __half g_combh[ML*DIMV];
__device__ __align__(16) __half g_o0[ML*DIMV];
__device__ __align__(16) __half g_o1[ML*DIMV];
__device__ __align__(16) __half g_o2[ML*DIMV];
__device__ float g_l0[ML*NH];
__device__ float g_l1[ML*NH];
__device__ float g_l2[ML*NH];

// ---------------- helpers ----------------
__device__ __forceinline__ uint32_t packh2(float lo, float hi) {
    __half2 h = __floats2half2_rn(lo, hi);
    return *reinterpret_cast<uint32_t*>(&h);
}
__device__ __forceinline__ void mma16(float* c, const uint32_t* a, uint32_t b0, uint32_t b1) {
    asm volatile(
        "mma.sync.aligned.m16n8k16.row.col.f32.f16.f16.f32 "
        "{%0,%1,%2,%3}, {%4,%5,%6,%7}, {%8,%9}, {%0,%1,%2,%3};"
        : "+f"(c[0]), "+f"(c[1]), "+f"(c[2]), "+f"(c[3])
        : "r"(a[0]), "r"(a[1]), "r"(a[2]), "r"(a[3]), "r"(b0), "r"(b1));
}
__device__ __forceinline__ void ldsm_x4(uint32_t* r, uint32_t addr) {
    asm volatile("ldmatrix.sync.aligned.m8n8.x4.shared.b16 {%0,%1,%2,%3}, [%4];"
        : "=r"(r[0]), "=r"(r[1]), "=r"(r[2]), "=r"(r[3]) : "r"(addr));
}
__device__ __forceinline__ void ldsm_x4t(uint32_t* r, uint32_t addr) {
    asm volatile("ldmatrix.sync.aligned.m8n8.x4.trans.shared.b16 {%0,%1,%2,%3}, [%4];"
        : "=r"(r[0]), "=r"(r[1]), "=r"(r[2]), "=r"(r[3]) : "r"(addr));
}
__device__ __forceinline__ uint32_t smem_u32(const void* p) {
    uint32_t a;
    asm("{ .reg .u64 t; cvta.to.shared.u64 t, %1; cvt.u32.u64 %0, t; }" : "=r"(a) : "l"(p));
    return a;
}
__device__ __forceinline__ void cp16(uint32_t dst, const void* src) {
    asm volatile("cp.async.cg.shared.global [%0], [%1], 16;" :: "r"(dst), "l"(src));
}
#define CP_COMMIT() asm volatile("cp.async.commit_group;" ::: "memory")
#define CP_WAIT1()  asm volatile("cp.async.wait_group 1;" ::: "memory")
#define CP_WAIT0()  asm volatile("cp.async.wait_group 0;" ::: "memory")

__device__ __forceinline__ float ex2f(float x) {
    float r;
    asm("ex2.approx.f32 %0, %1;" : "=f"(r) : "f"(x));
    return r;
}

// =====================================================================
// fp32 -> fp16 conversion kernels
// =====================================================================
__global__ __launch_bounds__(256) void conv_in(const float* __restrict__ q,
                                               const float* __restrict__ k,
                                               const float* __restrict__ v) {
    const float* src = (blockIdx.y == 0) ? q : (blockIdx.y == 1) ? k : v;
    __half* dst = (blockIdx.y == 0) ? g_xq : (blockIdx.y == 1) ? g_xk : g_xv;
    int i = blockIdx.x * blockDim.x + threadIdx.x;
    if (i >= ML * DIMV / 4) return;
    float4 a = ((const float4*)src)[i];
    ((__half2*)dst)[2*i]   = __floats2half2_rn(a.x, a.y);
    ((__half2*)dst)[2*i+1] = __floats2half2_rn(a.z, a.w);
}
__global__ __launch_bounds__(256) void conv_w(const float* __restrict__ wq,
                                              const float* __restrict__ wk,
                                              const float* __restrict__ wv,
                                              const float* __restrict__ wo) {
    const float* src = (blockIdx.y == 0) ? wq : (blockIdx.y == 1) ? wk :
                       (blockIdx.y == 2) ? wv : wo;
    __half* dst = (blockIdx.y == 0) ? g_wq : (blockIdx.y == 1) ? g_wk :
                  (blockIdx.y == 2) ? g_wv : g_wo;
    int i = blockIdx.x * blockDim.x + threadIdx.x;
    if (i >= DIMV * DIMV / 4) return;
    float4 a = ((const float4*)src)[i];
    ((__half2*)dst)[2*i]   = __floats2half2_rn(a.x, a.y);
    ((__half2*)dst)[2*i+1] = __floats2half2_rn(a.z, a.w);
}

// =====================================================================
// Pure fp16 GEMM: C[16384,512] = A @ W^T (+bias).
// CTA 128x128, 256 thr / 8 warps, warp tile 64x32, BK=64, ldmatrix.
// =====================================================================
#define GSTH 72
#define GHBUF (2*128*GSTH)
#define G_SMEM_BYTES (2*GHBUF*2)       // 73728

template <bool OUT_HALF>
__device__ __forceinline__ void gemm_body(const __half* __restrict__ A,
                                          const __half* __restrict__ W,
                                          const float* __restrict__ bias,
                                          float* __restrict__ Cf,
                                          __half* __restrict__ Ch,
                                          float oscale,
                                          __half* smg) {
    uint32_t sb = smem_u32(smg);
    const int t = threadIdx.x, lane = t & 31, w = t >> 5;
    const int g = lane >> 2, tg = lane & 3;
    const int m0 = blockIdx.x * 128, n0 = blockIdx.y * 128;
    const int wm = (w >> 2) * 64, wn = (w & 3) * 32;

    const int aRow = lane & 15,                 aCh = (lane >> 4) * 8;
    const int wRow = (lane & 7) + ((lane >> 4) & 1) * 8, wCh = ((lane >> 3) & 1) * 8;

    float c[4][4][4];
    #pragma unroll
    for (int i = 0; i < 4; i++)
        #pragma unroll
        for (int j = 0; j < 4; j++)
            #pragma unroll
            for (int q = 0; q < 4; q++) c[i][j][q] = 0.f;

    auto fill = [&](int ck, int buf) {
        #pragma unroll
        for (int r = 0; r < 4; r++) {
            int idx = t + r * 256;
            int row = idx >> 3, c8 = idx & 7;
            uint32_t dA = sb + (uint32_t)(buf * GHBUF + row * GSTH + c8 * 8) * 2u;
            cp16(dA, A + (size_t)(m0 + row) * 512 + ck * 64 + c8 * 8);
            uint32_t dW = sb + (uint32_t)(buf * GHBUF + 128 * GSTH + row * GSTH + c8 * 8) * 2u;
            cp16(dW, W + (size_t)(n0 + row) * 512 + ck * 64 + c8 * 8);
        }
        CP_COMMIT();
    };

    fill(0, 0);
    fill(1, 1);

    for (int ck = 0; ck < 8; ck++) {
        if (ck < 7) CP_WAIT1(); else CP_WAIT0();
        __syncthreads();
        uint32_t abase = sb + (uint32_t)((ck & 1) * GHBUF) * 2u;
        uint32_t wbase = abase + (uint32_t)(128 * GSTH) * 2u;
        #pragma unroll
        for (int ks = 0; ks < 4; ks++) {
            uint32_t af[4][4], bf[8];
            #pragma unroll
            for (int mt = 0; mt < 4; mt++)
                ldsm_x4(af[mt], abase +
                    (uint32_t)((wm + mt*16 + aRow) * GSTH + ks*16 + aCh) * 2u);
            ldsm_x4(bf,     wbase + (uint32_t)((wn + wRow)      * GSTH + ks*16 + wCh) * 2u);
            ldsm_x4(bf + 4, wbase + (uint32_t)((wn + 16 + wRow) * GSTH + ks*16 + wCh) * 2u);
            #pragma unroll
            for (int mt = 0; mt < 4; mt++)
                #pragma unroll
                for (int nt = 0; nt < 4; nt++)
                    mma16(c[mt][nt], af[mt], bf[nt*2], bf[nt*2+1]);
        }
        __syncthreads();
        if (ck + 2 < 8) fill(ck + 2, ck & 1);
    }

    #pragma unroll
    for (int mt = 0; mt < 4; mt++) {
        int row0 = m0 + wm + mt * 16 + g;
        #pragma unroll
        for (int nt = 0; nt < 4; nt++) {
            int col = n0 + wn + nt * 8 + 2 * tg;
            if (OUT_HALF) {
                *(__half2*)(Ch + (size_t)row0 * 512 + col) =
                    __floats2half2_rn(c[mt][nt][0] * oscale, c[mt][nt][1] * oscale);
                *(__half2*)(Ch + (size_t)(row0 + 8) * 512 + col) =
                    __floats2half2_rn(c[mt][nt][2] * oscale, c[mt][nt][3] * oscale);
            } else {
                float b0 = 0.f, b1 = 0.f;
                if (bias) { b0 = bias[col]; b1 = bias[col + 1]; }
                *(float2*)(Cf + (size_t)row0 * 512 + col) =
                    make_float2(c[mt][nt][0] + b0, c[mt][nt][1] + b1);
                *(float2*)(Cf + (size_t)(row0 + 8) * 512 + col) =
                    make_float2(c[mt][nt][2] + b0, c[mt][nt][3] + b1);
            }
        }
    }
}

__global__ __launch_bounds__(256, 2) void gemm_proj() {
    extern __shared__ __half smg[];
    const __half* A; const __half* W; __half* C; float sc;
    if (blockIdx.z == 0)      { A = g_xq; W = g_wq; C = g_qh; sc = QPRESCALE; }
    else if (blockIdx.z == 1) { A = g_xk; W = g_wk; C = g_kh; sc = 1.0f; }
    else                      { A = g_xv; W = g_wv; C = g_vh; sc = 1.0f; }
    gemm_body<true>(A, W, nullptr, nullptr, C, sc, smg);
}

__global__ __launch_bounds__(256, 2) void gemm_out(const float* __restrict__ bo,
                                                   float* __restrict__ out) {
    extern __shared__ __half smg[];
    gemm_body<false>(g_combh, g_wo, bo, out, nullptr, 1.0f, smg);
}

// =====================================================================
// fp16-mma flash attention — software-pipelined S/PV, 3-stage KV ring.
// CTA = 256 q rows of one (branch,b,seg,h) block -> 896 CTAs, 256 thr.
// Per key-half u: S(u) mmas, then PV(u-1) mmas (prev P, prev V), then
// exp(u) -> pf. Tensor pipe stays fed during the MUFU exp chain.
// smem: 3 x (K 64x72 + V 64x72) halves = 55296 B.
// =====================================================================
#define KSTH 72
#define ABUF (64*KSTH)
#define A_SMEM_BYTES (6*ABUF*2)        // 55296

__global__ __launch_bounds__(256, 1) void attn_mma() {
    extern __shared__ __half smh[];
    uint32_t sb = smem_u32(smh);
    const int t = threadIdx.x, lane = t & 31, w = t >> 5;
    const int g = lane >> 2, tg = lane & 3;

    int bid = blockIdx.x;
    int br, rem;
    if (bid < 512)      { br = 0; rem = bid; }
    else if (bid < 768) { br = 1; rem = bid - 512; }
    else                { br = 2; rem = bid - 768; }
    int sl, dr, nseg;
    if (br == 0)      { sl = 1024; dr = 1; nseg = 8; }
    else if (br == 1) { sl = 2048; dr = 2; nseg = 4; }
    else              { sl = 4096; dr = 4; nseg = 2; }
    int qs = rem & 3; rem >>= 2;
    int h  = rem & 7; rem >>= 3;
    int seg = rem % nseg;
    int b   = rem / nseg;
    int off = h / (NH / dr);
    __half* og = (br == 0) ? g_o0 : (br == 1) ? g_o1 : g_o2;
    float*  lg = (br == 0) ? g_l0 : (br == 1) ? g_l1 : g_l2;
    const size_t baseBL = (size_t)b * LL;

    // ---- stage all 256 Q rows (uses first 36864 B = buffers 0..1) ----
    #pragma unroll
    for (int i = 0; i < 8; i++) {
        int idx = t + i * 256;
        int row = idx >> 3, c8 = idx & 7;
        int p = seg * sl + (qs * 256 + row) * dr + off;
        cp16(sb + (uint32_t)(row * KSTH + c8 * 8) * 2u,
             g_qh + (baseBL + p) * 512 + h * 64 + c8 * 8);
    }
    CP_COMMIT();
    CP_WAIT0();
    __syncthreads();

    // ---- Q a-frags via ldmatrix.x4 ----
    uint32_t qa[2][4][4];
    {
        int rl = w * 32 + (lane & 15);
        int ch = (lane >> 4) * 8;
        #pragma unroll
        for (int mt = 0; mt < 2; mt++)
            #pragma unroll
            for (int ks = 0; ks < 4; ks++)
                ldsm_x4(qa[mt][ks],
                        sb + (uint32_t)((rl + mt*16) * KSTH + ks*16 + ch) * 2u);
    }
    __syncthreads();

    auto fill = [&](int kt, int buf) {
        #pragma unroll
        for (int i = 0; i < 2; i++) {
            int idx = t + i * 256;
            int row = idx >> 3, c8 = idx & 7;
            int p = seg * sl + (kt * 64 + row) * dr + off;
            size_t gidx = (baseBL + p) * 512 + h * 64 + c8 * 8;
            uint32_t dK = sb + (uint32_t)(buf * 2 * ABUF + row * KSTH + c8 * 8) * 2u;
            cp16(dK, g_kh + gidx);
            cp16(dK + ABUF * 2u, g_vh + gidx);
        }
        CP_COMMIT();
    };

    float oc[2][8][4];
    #pragma unroll
    for (int mt = 0; mt < 2; mt++)
        #pragma unroll
        for (int db = 0; db < 8; db++)
            oc[mt][db][0] = oc[mt][db][1] = oc[mt][db][2] = oc[mt][db][3] = 0.f;
    float rsum[2][4];
    #pragma unroll
    for (int mt = 0; mt < 2; mt++)
        rsum[mt][0] = rsum[mt][1] = rsum[mt][2] = rsum[mt][3] = 0.f;

    const int kKeyOff = (lane & 7) + ((lane >> 4) & 1) * 8;
    const int kColOff = ((lane >> 3) & 1) * 8;
    const int vKeyOff = (lane & 7) + ((lane >> 3) & 1) * 8;
    const int vColOff = ((lane >> 4) & 1) * 8;

    // S = Q K^T over one 32-key half
    auto do_S = [&](float sc[2][4][4], uint32_t kbase, int kh) {
        #pragma unroll
        for (int mt = 0; mt < 2; mt++)
            #pragma unroll
            for (int kb = 0; kb < 4; kb++)
                sc[mt][kb][0] = sc[mt][kb][1] = sc[mt][kb][2] = sc[mt][kb][3] = 0.f;
        #pragma unroll
        for (int ks = 0; ks < 4; ks++) {
            uint32_t bf[8];
            uint32_t ka = kbase +
                (uint32_t)((kh*32 + kKeyOff) * KSTH + kColOff + ks*16) * 2u;
            ldsm_x4(bf,     ka);
            ldsm_x4(bf + 4, ka + (uint32_t)(16 * KSTH) * 2u);
            #pragma unroll
            for (int mt = 0; mt < 2; mt++)
                #pragma unroll
                for (int kb = 0; kb < 4; kb++)
                    mma16(sc[mt][kb], qa[mt][ks], bf[kb*2], bf[kb*2+1]);
        }
    };

    // P = 2^S -> pf (PV a-frags); row sums via ones-mma
    auto do_exp = [&](float sc[2][4][4], uint32_t pf[2][2][4]) {
        #pragma unroll
        for (int mt = 0; mt < 2; mt++) {
            #pragma unroll
            for (int kbp = 0; kbp < 2; kbp++) {
                float a0 = ex2f(sc[mt][2*kbp][0]),   a1 = ex2f(sc[mt][2*kbp][1]);
                float a2 = ex2f(sc[mt][2*kbp][2]),   a3 = ex2f(sc[mt][2*kbp][3]);
                float b0 = ex2f(sc[mt][2*kbp+1][0]), b1 = ex2f(sc[mt][2*kbp+1][1]);
                float b2 = ex2f(sc[mt][2*kbp+1][2]), b3 = ex2f(sc[mt][2*kbp+1][3]);
                pf[mt][kbp][0] = packh2(a0, a1);
                pf[mt][kbp][1] = packh2(a2, a3);
                pf[mt][kbp][2] = packh2(b0, b1);
                pf[mt][kbp][3] = packh2(b2, b3);
                mma16(rsum[mt], pf[mt][kbp], ONESH2, ONESH2);
            }
        }
    };

    // O += P V over one 32-key half (prev P, prev V tile)
    auto do_PV = [&](uint32_t pf[2][2][4], uint32_t vbase, int kh) {
        #pragma unroll
        for (int kbp = 0; kbp < 2; kbp++) {
            int key0 = kh*32 + kbp*16;
            #pragma unroll
            for (int dbp = 0; dbp < 4; dbp++) {
                uint32_t vb[4];
                ldsm_x4t(vb, vbase +
                    (uint32_t)((key0 + vKeyOff) * KSTH + dbp*16 + vColOff) * 2u);
                mma16(oc[0][dbp*2],   pf[0][kbp], vb[0], vb[1]);
                mma16(oc[0][dbp*2+1], pf[0][kbp], vb[2], vb[3]);
                mma16(oc[1][dbp*2],   pf[1][kbp], vb[0], vb[1]);
                mma16(oc[1][dbp*2+1], pf[1][kbp], vb[2], vb[3]);
            }
        }
    };

    fill(0, 0);
    fill(1, 1);

    float scA[2][4][4], scB[2][4][4];
    uint32_t pf[2][2][4];
    uint32_t vbase_prev = 0;

    for (int kt = 0; kt < 16; kt++) {
        if (kt < 15) CP_WAIT1(); else CP_WAIT0();
        __syncthreads();                           // fill(kt) visible to all
        uint32_t kbase = sb + (uint32_t)((kt % 3) * 2 * ABUF) * 2u;
        uint32_t vbase = kbase + (uint32_t)ABUF * 2u;

        do_S(scA, kbase, 0);                       // u = 2kt
        if (kt > 0) do_PV(pf, vbase_prev, 1);      // consume u = 2kt-1 (V(kt-1) h1)
        __syncthreads();                           // V(kt-1)/K(kt-1) fully consumed
        if (kt < 14) fill(kt + 2, (kt + 2) % 3);   // overwrite buffer of kt-1
        do_exp(scA, pf);

        do_S(scB, kbase, 1);                       // u = 2kt+1
        do_PV(pf, vbase, 0);                       // consume u = 2kt (V(kt) h0)
        do_exp(scB, pf);

        vbase_prev = vbase;
    }
    do_PV(pf, vbase_prev, 1);                      // final: V(15) h1

    // ---- epilogue ----
    #pragma unroll
    for (int mt = 0; mt < 2; mt++) {
        #pragma unroll
        for (int rs = 0; rs < 2; rs++) {
            float rsv = rsum[mt][rs*2];
            int qrow = qs * 256 + w * 32 + mt * 16 + g + rs * 8;
            int p = seg * sl + qrow * dr + off;
            float inv = 1.f / rsv;
            __half* op = og + (baseBL + p) * 512 + h * 64;
            #pragma unroll
            for (int db = 0; db < 8; db++) {
                *(__half2*)(op + db * 8 + 2 * tg) =
                    __floats2half2_rn(oc[mt][db][rs*2+0] * inv,
                                      oc[mt][db][rs*2+1] * inv);
            }
            if (tg == 0) {
                float lse = logf(rsv);
                if (lse == 0.0f) lse = NEG_FILL;
                lg[(baseBL + p) * NH + h] = lse;
            }
        }
    }
}

// =====================================================================
// Combine branches (half inputs, half output).
// =====================================================================
__global__ __launch_bounds__(256) void combine_kernel() {
    int idx4 = blockIdx.x * blockDim.x + threadIdx.x;
    if (idx4 >= ML * DIMV / 4) return;
    int col4 = idx4 & 127;
    int row  = idx4 >> 7;
    int h    = col4 >> 4;
    int p    = row & (LL - 1);
    int li   = row * NH + h;

    float l1 = g_l0[li];
    float l2 = ((p & 1) == (h >> 2)) ? g_l1[li] : NEG_FILL;
    float l3 = ((p & 3) == (h >> 1)) ? g_l2[li] : NEG_FILL;
    float mm = fmaxf(l1, fmaxf(l2, l3));
    float w1 = __expf(l1 - mm), w2 = __expf(l2 - mm), w3 = __expf(l3 - mm);
    float inv = 1.f / (w1 + w2 + w3);
    w1 *= inv; w2 *= inv; w3 *= inv;

    __half2 a0 = ((const __half2*)g_o0)[2*idx4], a1 = ((const __half2*)g_o0)[2*idx4+1];
    __half2 b0 = ((const __half2*)g_o1)[2*idx4], b1 = ((const __half2*)g_o1)[2*idx4+1];
    __half2 c0 = ((const __half2*)g_o2)[2*idx4], c1 = ((const __half2*)g_o2)[2*idx4+1];
    float2 af0 = __half22float2(a0), af1 = __half22float2(a1);
    float2 bf0 = __half22float2(b0), bf1 = __half22float2(b1);
    float2 cf0 = __half22float2(c0), cf1 = __half22float2(c1);

    float ox = w1*af0.x + w2*bf0.x + w3*cf0.x;
    float oy = w1*af0.y + w2*bf0.y + w3*cf0.y;
    float oz = w1*af1.x + w2*bf1.x + w3*cf1.x;
    float ow = w1*af1.y + w2*bf1.y + w3*cf1.y;
    ((__half2*)g_combh)[2*idx4]   = __floats2half2_rn(ox, oy);
    ((__half2*)g_combh)[2*idx4+1] = __floats2half2_rn(oz, ow);
}

// =====================================================================
extern "C" void kernel_launch(void* const* d_in, const int* in_sizes, int n_in,
                              void* d_out, int out_size) {
    (void)in_sizes; (void)n_in; (void)out_size;
    const float* query = (const float*)d_in[0];
    const float* key_  = (const float*)d_in[1];
    const float* value = (const float*)d_in[2];
    const float* Wq    = (const float*)d_in[3];
    const float* Wk    = (const float*)d_in[4];
    const float* Wv    = (const float*)d_in[5];
    const float* Wo    = (const float*)d_in[6];
    const float* bo    = (const float*)d_in[7];
    float* out = (float*)d_out;

    cudaFuncSetAttribute(gemm_proj, cudaFuncAttributeMaxDynamicSharedMemorySize, G_SMEM_BYTES);
    cudaFuncSetAttribute(gemm_out,  cudaFuncAttributeMaxDynamicSharedMemorySize, G_SMEM_BYTES);
    cudaFuncSetAttribute(attn_mma,  cudaFuncAttributeMaxDynamicSharedMemorySize, A_SMEM_BYTES);

    {
        dim3 gi((ML * DIMV / 4 + 255) / 256, 3);
        conv_in<<<gi, 256>>>(query, key_, value);
        dim3 gw((DIMV * DIMV / 4 + 255) / 256, 4);
        conv_w<<<gw, 256>>>(Wq, Wk, Wv, Wo);
    }

    dim3 gp(128, 4, 3);
    gemm_proj<<<gp, 256, G_SMEM_BYTES>>>();

    attn_mma<<<896, 256, A_SMEM_BYTES>>>();

    combine_kernel<<<ML * DIMV / 4 / 256, 256>>>();

    dim3 go(128, 4);
    gemm_out<<<go, 256, G_SMEM_BYTES>>>(bo, out);
}